// round 12
// baseline (speedup 1.0000x reference)
#include <cuda_runtime.h>
#include <cuda_bf16.h>
#include <math.h>
#include <stdint.h>

#define NN 16384
#define DD 512
#define BSZ 16
#define MM 256
#define HH 8
#define DHH 64
#define LL 4
#define EE 262144
#define EPSV 1e-5f

// ---------------- scratch (static device globals) ---------------------------
__device__ float g_h [(size_t)NN*DD];
__device__ float g_b1[(size_t)NN*DD];
__device__ float g_b2[(size_t)NN*DD];
__device__ float g_b3[(size_t)NN*DD];
__device__ float g_kb[(size_t)BSZ*MM*DD];
__device__ float g_vb[(size_t)BSZ*MM*DD];
__device__ float g_f [(size_t)NN*2048];
__device__ __nv_bfloat16 g_cs[(size_t)2*BSZ*MM*DD];
__device__ float g_deg [NN];
__device__ float g_dinv[NN];
__device__ int   g_edge[2*EE];
__device__ int   g_flag;
__device__ float g_sum  [DD];
__device__ float g_sumsq[DD];
#define WT_TOTAL 17301504ULL
__device__ __nv_bfloat16 g_bt0[WT_TOTAL];
__device__ __nv_bfloat16 g_bt1[WT_TOTAL];

// ======================= helpers =============================================
__device__ __forceinline__ uint32_t smem_u32(const void* p) {
    uint32_t a;
    asm("{ .reg .u64 t; cvta.to.shared.u64 t, %1; cvt.u32.u64 %0, t; }"
        : "=r"(a) : "l"(p));
    return a;
}
__device__ __forceinline__ uint32_t sw64(int row, int c) {
    return ((uint32_t)row << 6) + (((uint32_t)(c ^ ((row >> 1) & 3))) << 4);
}
__device__ __forceinline__ uint32_t asw(int row, int ch) {
    return ((uint32_t)row << 7) + (((uint32_t)(ch ^ (row & 7))) << 4);
}

#define LDSM_X4(r, addr) \
    asm volatile("ldmatrix.sync.aligned.m8n8.x4.shared.b16 {%0,%1,%2,%3}, [%4];" \
        : "=r"((r)[0]), "=r"((r)[1]), "=r"((r)[2]), "=r"((r)[3]) : "r"(addr))
#define LDSM_X4_T(r, addr) \
    asm volatile("ldmatrix.sync.aligned.m8n8.x4.trans.shared.b16 {%0,%1,%2,%3}, [%4];" \
        : "=r"((r)[0]), "=r"((r)[1]), "=r"((r)[2]), "=r"((r)[3]) : "r"(addr))

__device__ __forceinline__ void mma16816(float* c, const uint32_t* a, const uint32_t* b) {
    asm volatile("mma.sync.aligned.m16n8k16.row.col.f32.bf16.bf16.f32 "
        "{%0,%1,%2,%3}, {%4,%5,%6,%7}, {%8,%9}, {%0,%1,%2,%3};"
        : "+f"(c[0]), "+f"(c[1]), "+f"(c[2]), "+f"(c[3])
        : "r"(a[0]), "r"(a[1]), "r"(a[2]), "r"(a[3]), "r"(b[0]), "r"(b[1]));
}

#define CP_ASYNC16(dst, src) \
    asm volatile("cp.async.cg.shared.global [%0], [%1], 16;" :: "r"(dst), "l"(src))
#define CP_COMMIT()  asm volatile("cp.async.commit_group;" ::: "memory")
#define CP_WAIT1()   asm volatile("cp.async.wait_group 1;" ::: "memory")

__device__ __forceinline__ void split2(float a, float b, uint32_t& hi, uint32_t& lo) {
    __nv_bfloat16 ha = __float2bfloat16(a), hb = __float2bfloat16(b);
    __nv_bfloat162 H = __halves2bfloat162(ha, hb);
    __nv_bfloat162 L = __halves2bfloat162(
        __float2bfloat16(a - __bfloat162float(ha)),
        __float2bfloat16(b - __bfloat162float(hb)));
    hi = *(uint32_t*)&H; lo = *(uint32_t*)&L;
}

// ---------------- weight transpose + bf16 split (z-batched over layers) ------
// perm != 0: geglu column interleave — output row n' : orig col c<2048 -> 2c,
// c>=2048 -> 2(c-2048)+1, so (val,gate) pairs are adjacent columns.
__global__ void wsplit(const float* __restrict__ W, __nv_bfloat16* __restrict__ O0,
                       __nv_bfloat16* __restrict__ O1, int K, int N,
                       size_t wstride, size_t ostride, int perm) {
    __shared__ float t[32][33];
    W  += (size_t)blockIdx.z * wstride;
    O0 += (size_t)blockIdx.z * ostride;
    O1 += (size_t)blockIdx.z * ostride;
    int bn = blockIdx.x * 32, bk = blockIdx.y * 32;
    int tx = threadIdx.x, ty = threadIdx.y;
    for (int i = ty; i < 32; i += 8)
        t[i][tx] = W[(size_t)(bk + i) * N + bn + tx];
    __syncthreads();
    for (int i = ty; i < 32; i += 8) {
        float v = t[tx][i];
        __nv_bfloat16 h0 = __float2bfloat16(v);
        float r = v - __bfloat162float(h0);
        int n = bn + i;
        int dst = perm ? ((n < 2048) ? 2 * n : 2 * (n - 2048) + 1) : n;
        size_t o = (size_t)dst * K + bk + tx;
        O0[o] = h0;
        O1[o] = __float2bfloat16(r);
    }
}

// ---------------- fp32 -> split-bf16 planes ----------------------------------
__global__ void fsplit(const float* __restrict__ in, __nv_bfloat16* __restrict__ hi,
                       __nv_bfloat16* __restrict__ lo) {
    size_t i = (size_t)blockIdx.x * 256 + threadIdx.x;
    float4 v = ((const float4*)in)[i];
    uint32_t h0, h1, l0, l1;
    split2(v.x, v.y, h0, l0);
    split2(v.z, v.w, h1, l1);
    ((uint2*)hi)[i] = make_uint2(h0, h1);
    ((uint2*)lo)[i] = make_uint2(l0, l1);
}

// ---------------- HMMA split-bf16 GEMM, occupancy 2 --------------------------
// fuse=0: C = A*W (+bias)(+add) fp32.
// fuse=1: GEGLU epilogue — adjacent column pairs (val,gate); writes split-bf16
//         f planes [M][N/2]; bias = original geglu bias (val at pc, gate at 2048+pc).
#define MM_SMEM 98304
#define STG 32768

__device__ __forceinline__ void mm_issue(
    const __nv_bfloat16* __restrict__ A0, const __nv_bfloat16* __restrict__ A1,
    const __nv_bfloat16* __restrict__ B0, const __nv_bfloat16* __restrict__ B1,
    uint32_t sb, int stage, int bm, int bn, int K, int kc, int tid)
{
    uint32_t a0b = sb + stage * STG, a1b = a0b + 8192;
    uint32_t b0b = a0b + 16384, b1b = a0b + 24576;
#pragma unroll
    for (int i = 0; i < 2; i++) {
        int idx = i * 256 + tid;
        int r = idx >> 2, c = idx & 3;
        uint32_t d = sw64(r, c);
        size_t sa = (size_t)(bm + r) * K + kc * 32 + c * 8;
        size_t sbx = (size_t)(bn + r) * K + kc * 32 + c * 8;
        CP_ASYNC16(a0b + d, A0 + sa);
        CP_ASYNC16(a1b + d, A1 + sa);
        CP_ASYNC16(b0b + d, B0 + sbx);
        CP_ASYNC16(b1b + d, B1 + sbx);
    }
}

__global__ __launch_bounds__(256, 2)
void mm_gemm(const __nv_bfloat16* __restrict__ A0, const __nv_bfloat16* __restrict__ A1,
             const __nv_bfloat16* __restrict__ B0, const __nv_bfloat16* __restrict__ B1,
             float* __restrict__ C, int M, int N, int K,
             const float* __restrict__ bias, const float* __restrict__ add,
             __nv_bfloat16* __restrict__ ohi, __nv_bfloat16* __restrict__ olo,
             int fuse)
{
    extern __shared__ char smem[];
    uint32_t sb = smem_u32(smem);
    const int tid = threadIdx.x, wid = tid >> 5, lane = tid & 31;
    const int bm = blockIdx.y * 128, bn = blockIdx.x * 128;
    const int wm = wid >> 2, wn = wid & 3;
    const int nch = K >> 5;

    float acc[4][4][4];
#pragma unroll
    for (int i = 0; i < 4; i++)
#pragma unroll
        for (int j = 0; j < 4; j++)
#pragma unroll
            for (int k = 0; k < 4; k++) acc[i][j][k] = 0.f;

    mm_issue(A0, A1, B0, B1, sb, 0, bm, bn, K, 0, tid); CP_COMMIT();
    mm_issue(A0, A1, B0, B1, sb, 1, bm, bn, K, 1, tid); CP_COMMIT();

    int pc = 0, pi = 2;
    for (int kc = 0; kc < nch; kc++) {
        CP_WAIT1();
        __syncthreads();
        if (kc + 2 < nch)
            mm_issue(A0, A1, B0, B1, sb, pi, bm, bn, K, kc + 2, tid);
        CP_COMMIT();

        const uint32_t stA0 = sb + pc * STG, stA1 = stA0 + 8192;
        const uint32_t stB0 = stA0 + 16384, stB1 = stA0 + 24576;
#pragma unroll
        for (int s = 0; s < 2; s++) {
            uint32_t rb0[2][4], rb1[2][4];
#pragma unroll
            for (int g = 0; g < 2; g++) {
                int row = wn * 32 + g * 16 + ((lane >> 4) << 3) + (lane & 7);
                int c = 2 * s + ((lane >> 3) & 1);
                uint32_t off = sw64(row, c);
                LDSM_X4(rb0[g], stB0 + off);
                LDSM_X4(rb1[g], stB1 + off);
            }
            uint32_t a[4][4];
            int arow = wm * 64 + (lane & 15);
            int ac = 2 * s + (lane >> 4);
#pragma unroll
            for (int mf = 0; mf < 4; mf++)
                LDSM_X4(a[mf], stA0 + sw64(arow + mf * 16, ac));
#pragma unroll
            for (int mf = 0; mf < 4; mf++)
#pragma unroll
                for (int g = 0; g < 2; g++) {
                    mma16816(acc[mf][2*g],   a[mf], rb0[g]);
                    mma16816(acc[mf][2*g+1], a[mf], rb0[g] + 2);
                    mma16816(acc[mf][2*g],   a[mf], rb1[g]);
                    mma16816(acc[mf][2*g+1], a[mf], rb1[g] + 2);
                }
#pragma unroll
            for (int mf = 0; mf < 4; mf++)
                LDSM_X4(a[mf], stA1 + sw64(arow + mf * 16, ac));
#pragma unroll
            for (int mf = 0; mf < 4; mf++)
#pragma unroll
                for (int g = 0; g < 2; g++) {
                    mma16816(acc[mf][2*g],   a[mf], rb0[g]);
                    mma16816(acc[mf][2*g+1], a[mf], rb0[g] + 2);
                }
        }
        pc = (pc == 2) ? 0 : pc + 1;
        pi = (pi == 2) ? 0 : pi + 1;
    }

    if (fuse) {
        // GEGLU epilogue: columns (c0, c0+1) = (val, gate) of pair c0/2
#pragma unroll
        for (int mf = 0; mf < 4; mf++) {
#pragma unroll
            for (int ng = 0; ng < 4; ng++) {
                int r0 = bm + wm * 64 + mf * 16 + (lane >> 2);
                int c0 = bn + wn * 32 + ng * 8 + ((lane & 3) << 1);
                int pcx = c0 >> 1;
                float bv = bias[pcx], bg = bias[2048 + pcx];
                float val = acc[mf][ng][0] + bv, gate = acc[mf][ng][1] + bg;
                float f0 = val * 0.5f * gate * (1.f + erff(gate * 0.70710678f));
                val = acc[mf][ng][2] + bv; gate = acc[mf][ng][3] + bg;
                float f1 = val * 0.5f * gate * (1.f + erff(gate * 0.70710678f));
                __nv_bfloat16 h0 = __float2bfloat16(f0);
                ohi[(size_t)r0 * 2048 + pcx] = h0;
                olo[(size_t)r0 * 2048 + pcx] =
                    __float2bfloat16(f0 - __bfloat162float(h0));
                __nv_bfloat16 h1 = __float2bfloat16(f1);
                ohi[(size_t)(r0 + 8) * 2048 + pcx] = h1;
                olo[(size_t)(r0 + 8) * 2048 + pcx] =
                    __float2bfloat16(f1 - __bfloat162float(h1));
            }
        }
        return;
    }

#pragma unroll
    for (int mf = 0; mf < 4; mf++) {
#pragma unroll
        for (int ng = 0; ng < 4; ng++) {
            int r0 = bm + wm * 64 + mf * 16 + (lane >> 2);
            int c0 = bn + wn * 32 + ng * 8 + ((lane & 3) << 1);
            float2 v0 = make_float2(acc[mf][ng][0], acc[mf][ng][1]);
            float2 v1 = make_float2(acc[mf][ng][2], acc[mf][ng][3]);
            if (bias) {
                float2 bb = *(const float2*)(bias + c0);
                v0.x += bb.x; v0.y += bb.y; v1.x += bb.x; v1.y += bb.y;
            }
            if (add) {
                float2 a0v = *(const float2*)(add + (size_t)r0 * N + c0);
                float2 a1v = *(const float2*)(add + (size_t)(r0 + 8) * N + c0);
                v0.x += a0v.x; v0.y += a0v.y; v1.x += a1v.x; v1.y += a1v.y;
            }
            *(float2*)(C + (size_t)r0 * N + c0) = v0;
            *(float2*)(C + (size_t)(r0 + 8) * N + c0) = v1;
        }
    }
}

// ---------------- edge-index dtype detect + convert ------------------------
__global__ void detect_kernel(const int* __restrict__ e32) {
    __shared__ int any;
    if (threadIdx.x == 0) any = 0;
    __syncthreads();
    int bad = 0;
    for (int i = threadIdx.x; i < 4096; i += 256)
        if (e32[2*i + 1] != 0) bad = 1;
    if (bad) any = 1;
    __syncthreads();
    if (threadIdx.x == 0) g_flag = (any == 0) ? 1 : 0;
}

__global__ void convert_kernel(const void* __restrict__ e) {
    int i = blockIdx.x * 256 + threadIdx.x;
    if (i >= 2*EE) return;
    g_edge[i] = g_flag ? (int)((const long long*)e)[i] : ((const int*)e)[i];
}

__global__ void zero_stats() {
    int i = blockIdx.x * 256 + threadIdx.x;
    if (i < NN) g_deg[i] = 0.f;
    if (i < DD) { g_sum[i] = 0.f; g_sumsq[i] = 0.f; }
}

__global__ void deg_kernel() {
    int e = blockIdx.x * 256 + threadIdx.x;
    if (e < EE) atomicAdd(&g_deg[g_edge[EE + e]], 1.f);
}

__global__ void dinv_kernel() {
    int i = blockIdx.x * 256 + threadIdx.x;
    if (i < NN) g_dinv[i] = rsqrtf(g_deg[i] + 1.f);
}

// ---------------- BatchNorm --------------------------------------------------
__global__ void bn_partial(const float* __restrict__ x) {
    int col = blockIdx.x * 256 + threadIdx.x;
    int r0  = blockIdx.y * 1024;
    float s = 0.f, ss = 0.f;
    for (int r = r0; r < r0 + 1024; r++) {
        float v = x[(size_t)r * DD + col];
        s += v; ss += v * v;
    }
    atomicAdd(&g_sum[col], s);
    atomicAdd(&g_sumsq[col], ss);
}

__global__ void bn_apply(const float* __restrict__ x, const float* __restrict__ w,
                         const float* __restrict__ b, __nv_bfloat16* __restrict__ hi,
                         __nv_bfloat16* __restrict__ lo) {
    size_t i4 = (size_t)blockIdx.x * 256 + threadIdx.x;
    int c4 = (int)(i4 & 127) * 4;
    float4 xv = ((const float4*)x)[i4];
    float4 sm = *(const float4*)(g_sum + c4);
    float4 sq = *(const float4*)(g_sumsq + c4);
    float4 wv = *(const float4*)(w + c4);
    float4 bv = *(const float4*)(b + c4);
    float4 o;
    {
        float mu = sm.x / NN, var = sq.x / NN - mu*mu;
        o.x = (xv.x - mu) * rsqrtf(var + EPSV) * wv.x + bv.x;
        mu = sm.y / NN; var = sq.y / NN - mu*mu;
        o.y = (xv.y - mu) * rsqrtf(var + EPSV) * wv.y + bv.y;
        mu = sm.z / NN; var = sq.z / NN - mu*mu;
        o.z = (xv.z - mu) * rsqrtf(var + EPSV) * wv.z + bv.z;
        mu = sm.w / NN; var = sq.w / NN - mu*mu;
        o.w = (xv.w - mu) * rsqrtf(var + EPSV) * wv.w + bv.w;
    }
    uint32_t h0, h1, l0, l1;
    split2(o.x, o.y, h0, l0);
    split2(o.z, o.w, h1, l1);
    ((uint2*)hi)[i4] = make_uint2(h0, h1);
    ((uint2*)lo)[i4] = make_uint2(l0, l1);
}

// ---------------- LayerNorm -> split planes ----------------------------------
__global__ void ln_kernel(const float* __restrict__ x, const float* __restrict__ w,
                          const float* __restrict__ b, __nv_bfloat16* __restrict__ hi,
                          __nv_bfloat16* __restrict__ lo) {
    int warp = (blockIdx.x * blockDim.x + threadIdx.x) >> 5;
    int lane = threadIdx.x & 31;
    if (warp >= NN) return;
    const float4* xr = (const float4*)(x + (size_t)warp * DD);
    float4 v[4];
    float s = 0.f, ss = 0.f;
#pragma unroll
    for (int i = 0; i < 4; i++) {
        v[i] = xr[lane + 32*i];
        s  += v[i].x + v[i].y + v[i].z + v[i].w;
        ss += v[i].x*v[i].x + v[i].y*v[i].y + v[i].z*v[i].z + v[i].w*v[i].w;
    }
#pragma unroll
    for (int o = 16; o; o >>= 1) {
        s  += __shfl_xor_sync(0xffffffffu, s,  o);
        ss += __shfl_xor_sync(0xffffffffu, ss, o);
    }
    float mean = s * (1.f / DD);
    float var  = ss * (1.f / DD) - mean * mean;
    float rs   = rsqrtf(var + EPSV);
    uint2* hr = (uint2*)(hi + (size_t)warp * DD);
    uint2* lr = (uint2*)(lo + (size_t)warp * DD);
    const float4* wr = (const float4*)w;
    const float4* br = (const float4*)b;
#pragma unroll
    for (int i = 0; i < 4; i++) {
        float4 wv = wr[lane + 32*i], bv = br[lane + 32*i], o4;
        o4.x = (v[i].x - mean) * rs * wv.x + bv.x;
        o4.y = (v[i].y - mean) * rs * wv.y + bv.y;
        o4.z = (v[i].z - mean) * rs * wv.z + bv.z;
        o4.w = (v[i].w - mean) * rs * wv.w + bv.w;
        uint32_t h0, h1, l0, l1;
        split2(o4.x, o4.y, h0, l0);
        split2(o4.z, o4.w, h1, l1);
        hr[lane + 32*i] = make_uint2(h0, h1);
        lr[lane + 32*i] = make_uint2(l0, l1);
    }
}

// ---------------- GCN scatter ------------------------------------------------
__global__ void gcn_init(const float* __restrict__ hw, const float* __restrict__ bias,
                         const float* __restrict__ extra, float* __restrict__ out) {
    size_t i = (size_t)blockIdx.x * 256 + threadIdx.x;
    int r = (int)(i >> 9), c = (int)(i & 511);
    float dv = g_dinv[r];
    float v = hw[i] * dv * dv + bias[c];
    if (extra) v += extra[i];
    out[i] = v;
}

__global__ void gcn_scatter(const float* __restrict__ hw, float* __restrict__ out) {
    int wid  = (blockIdx.x * blockDim.x + threadIdx.x) >> 5;
    int lane = threadIdx.x & 31;
    if (wid >= EE) return;
    int s = g_edge[wid], d = g_edge[EE + wid];
    float w = g_dinv[s] * g_dinv[d];
    const float4* hp = (const float4*)(hw + (size_t)s * DD);
    float4* op = (float4*)(out + (size_t)d * DD);
#pragma unroll
    for (int i = 0; i < 4; i++) {
        int c = lane + 32 * i;
        float4 v = hp[c];
        v.x *= w; v.y *= w; v.z *= w; v.w *= w;
        atomicAdd(op + c, v);
    }
}

// ---------------- HMMA cross-attention (split-bf16, online softmax) ----------
#define ATT_SMEM 196608
#define OQH 0
#define OQL 32768
#define OKH 65536
#define OKL 98304
#define OVH 131072
#define OVL 163840

__global__ __launch_bounds__(256, 1) void attn_kernel(
    const float* __restrict__ Q, const float* __restrict__ Kc,
    const float* __restrict__ Vc, __nv_bfloat16* __restrict__ Ohi,
    __nv_bfloat16* __restrict__ Olo)
{
    extern __shared__ char smem[];
    uint32_t sb = smem_u32(smem);
    const int h = blockIdx.x, b = blockIdx.y, qc = blockIdx.z;
    const int tid = threadIdx.x, wid = tid >> 5, lane = tid & 31;
    const int qbase = b * 1024 + qc * 256;
    const int kbase = b * 256;

#pragma unroll 1
    for (int i = 0; i < 8; i++) {
        int idx = i * 256 + tid;
        int row = idx >> 3, ch = idx & 7;
        uint32_t d = asw(row, ch);
        uint32_t h0,h1,h2,h3,l0,l1,l2,l3;
        {
            const float* p = Q + (size_t)(qbase + row) * DD + h * DHH + ch * 8;
            float4 v0 = *(const float4*)p, v1 = *(const float4*)(p + 4);
            split2(v0.x, v0.y, h0, l0); split2(v0.z, v0.w, h1, l1);
            split2(v1.x, v1.y, h2, l2); split2(v1.z, v1.w, h3, l3);
            *(uint4*)(smem + OQH + d) = make_uint4(h0, h1, h2, h3);
            *(uint4*)(smem + OQL + d) = make_uint4(l0, l1, l2, l3);
        }
        {
            const float* p = Kc + (size_t)(kbase + row) * DD + h * DHH + ch * 8;
            float4 v0 = *(const float4*)p, v1 = *(const float4*)(p + 4);
            split2(v0.x, v0.y, h0, l0); split2(v0.z, v0.w, h1, l1);
            split2(v1.x, v1.y, h2, l2); split2(v1.z, v1.w, h3, l3);
            *(uint4*)(smem + OKH + d) = make_uint4(h0, h1, h2, h3);
            *(uint4*)(smem + OKL + d) = make_uint4(l0, l1, l2, l3);
        }
        {
            const float* p = Vc + (size_t)(kbase + row) * DD + h * DHH + ch * 8;
            float4 v0 = *(const float4*)p, v1 = *(const float4*)(p + 4);
            split2(v0.x, v0.y, h0, l0); split2(v0.z, v0.w, h1, l1);
            split2(v1.x, v1.y, h2, l2); split2(v1.z, v1.w, h3, l3);
            *(uint4*)(smem + OVH + d) = make_uint4(h0, h1, h2, h3);
            *(uint4*)(smem + OVL + d) = make_uint4(l0, l1, l2, l3);
        }
    }
    __syncthreads();

    const int wq = wid * 32;
    float oacc[2][8][4];
    float mrow[2][2], srow[2][2];
#pragma unroll
    for (int mf = 0; mf < 2; mf++) {
        mrow[mf][0] = -1e30f; mrow[mf][1] = -1e30f;
        srow[mf][0] = 0.f;    srow[mf][1] = 0.f;
#pragma unroll
        for (int nf = 0; nf < 8; nf++)
#pragma unroll
            for (int e = 0; e < 4; e++) oacc[mf][nf][e] = 0.f;
    }

#pragma unroll 1
    for (int kc4 = 0; kc4 < 4; kc4++) {
        float sacc[2][8][4];
#pragma unroll
        for (int mf = 0; mf < 2; mf++)
#pragma unroll
            for (int nf = 0; nf < 8; nf++)
#pragma unroll
                for (int e = 0; e < 4; e++) sacc[mf][nf][e] = 0.f;

#pragma unroll
        for (int ds = 0; ds < 4; ds++) {
            uint32_t qh[2][4], ql[2][4];
            int qrow = wq + (lane & 15);
            int qch = 2 * ds + (lane >> 4);
            LDSM_X4(qh[0], sb + OQH + asw(qrow, qch));
            LDSM_X4(qh[1], sb + OQH + asw(qrow + 16, qch));
            LDSM_X4(ql[0], sb + OQL + asw(qrow, qch));
            LDSM_X4(ql[1], sb + OQL + asw(qrow + 16, qch));
#pragma unroll
            for (int g = 0; g < 4; g++) {
                int krow = kc4 * 64 + g * 16 + ((lane >> 4) << 3) + (lane & 7);
                int kch = 2 * ds + ((lane >> 3) & 1);
                uint32_t kh[4], kl[4];
                LDSM_X4(kh, sb + OKH + asw(krow, kch));
                LDSM_X4(kl, sb + OKL + asw(krow, kch));
#pragma unroll
                for (int mf = 0; mf < 2; mf++) {
                    mma16816(sacc[mf][2*g],   qh[mf], kh);
                    mma16816(sacc[mf][2*g+1], qh[mf], kh + 2);
                    mma16816(sacc[mf][2*g],   qh[mf], kl);
                    mma16816(sacc[mf][2*g+1], qh[mf], kl + 2);
                    mma16816(sacc[mf][2*g],   ql[mf], kh);
                    mma16816(sacc[mf][2*g+1], ql[mf], kh + 2);
                }
            }
        }

#pragma unroll
        for (int mf = 0; mf < 2; mf++) {
            float mx0 = -1e30f, mx1 = -1e30f;
#pragma unroll
            for (int nf = 0; nf < 8; nf++) {
#pragma unroll
                for (int e = 0; e < 4; e++) sacc[mf][nf][e] *= 0.125f;
                mx0 = fmaxf(mx0, fmaxf(sacc[mf][nf][0], sacc[mf][nf][1]));
                mx1 = fmaxf(mx1, fmaxf(sacc[mf][nf][2], sacc[mf][nf][3]));
            }
            mx0 = fmaxf(mx0, __shfl_xor_sync(0xffffffffu, mx0, 1));
            mx0 = fmaxf(mx0, __shfl_xor_sync(0xffffffffu, mx0, 2));
            mx1 = fmaxf(mx1, __shfl_xor_sync(0xffffffffu, mx1, 1));
            mx1 = fmaxf(mx1, __shfl_xor_sync(0xffffffffu, mx1, 2));
            float nm0 = fmaxf(mrow[mf][0], mx0);
            float nm1 = fmaxf(mrow[mf][1], mx1);
            float c0 = __expf(mrow[mf][0] - nm0);
            float c1 = __expf(mrow[mf][1] - nm1);
            mrow[mf][0] = nm0; mrow[mf][1] = nm1;
            srow[mf][0] *= c0; srow[mf][1] *= c1;
#pragma unroll
            for (int nf = 0; nf < 8; nf++) {
                oacc[mf][nf][0] *= c0; oacc[mf][nf][1] *= c0;
                oacc[mf][nf][2] *= c1; oacc[mf][nf][3] *= c1;
                float p0 = __expf(sacc[mf][nf][0] - nm0);
                float p1 = __expf(sacc[mf][nf][1] - nm0);
                float p2 = __expf(sacc[mf][nf][2] - nm1);
                float p3 = __expf(sacc[mf][nf][3] - nm1);
                srow[mf][0] += p0 + p1;
                srow[mf][1] += p2 + p3;
                sacc[mf][nf][0] = p0; sacc[mf][nf][1] = p1;
                sacc[mf][nf][2] = p2; sacc[mf][nf][3] = p3;
            }
        }

#pragma unroll
        for (int kk = 0; kk < 4; kk++) {
            uint32_t p0f[2][4], p1f[2][4];
#pragma unroll
            for (int mf = 0; mf < 2; mf++) {
                const float* s0 = sacc[mf][2*kk];
                const float* s1 = sacc[mf][2*kk+1];
                split2(s0[0], s0[1], p0f[mf][0], p1f[mf][0]);
                split2(s0[2], s0[3], p0f[mf][1], p1f[mf][1]);
                split2(s1[0], s1[1], p0f[mf][2], p1f[mf][2]);
                split2(s1[2], s1[3], p0f[mf][3], p1f[mf][3]);
            }
            int vrow = kc4 * 64 + kk * 16 + (lane & 15);
#pragma unroll
            for (int g = 0; g < 4; g++) {
                int vch = 2 * g + (lane >> 4);
                uint32_t vh[4], vl[4];
                LDSM_X4_T(vh, sb + OVH + asw(vrow, vch));
                LDSM_X4_T(vl, sb + OVL + asw(vrow, vch));
#pragma unroll
                for (int mf = 0; mf < 2; mf++) {
                    mma16816(oacc[mf][2*g],   p0f[mf], vh);
                    mma16816(oacc[mf][2*g+1], p0f[mf], vh + 2);
                    mma16816(oacc[mf][2*g],   p0f[mf], vl);
                    mma16816(oacc[mf][2*g+1], p0f[mf], vl + 2);
                    mma16816(oacc[mf][2*g],   p1f[mf], vh);
                    mma16816(oacc[mf][2*g+1], p1f[mf], vh + 2);
                }
            }
        }
    }

#pragma unroll
    for (int mf = 0; mf < 2; mf++) {
        float s0 = srow[mf][0], s1 = srow[mf][1];
        s0 += __shfl_xor_sync(0xffffffffu, s0, 1);
        s0 += __shfl_xor_sync(0xffffffffu, s0, 2);
        s1 += __shfl_xor_sync(0xffffffffu, s1, 1);
        s1 += __shfl_xor_sync(0xffffffffu, s1, 2);
        float i0 = 1.f / s0, i1 = 1.f / s1;
        int r0 = qbase + wq + mf * 16 + (lane >> 2);
#pragma unroll
        for (int nf = 0; nf < 8; nf++) {
            int c = h * DHH + nf * 8 + ((lane & 3) << 1);
            uint32_t hh, lv;
            split2(oacc[mf][nf][0] * i0, oacc[mf][nf][1] * i0, hh, lv);
            *(uint32_t*)(Ohi + (size_t)r0 * DD + c) = hh;
            *(uint32_t*)(Olo + (size_t)r0 * DD + c) = lv;
            split2(oacc[mf][nf][2] * i1, oacc[mf][nf][3] * i1, hh, lv);
            *(uint32_t*)(Ohi + (size_t)(r0 + 8) * DD + c) = hh;
            *(uint32_t*)(Olo + (size_t)(r0 + 8) * DD + c) = lv;
        }
    }
}

// ---------------- host orchestration ----------------------------------------
extern "C" void kernel_launch(void* const* d_in, const int* in_sizes, int n_in,
                              void* d_out, int out_size)
{
    const float* x        = (const float*)d_in[0];
    const void*  edges    = d_in[1];
    const float* cond     = (const float*)d_in[2];
    const float* bn_w     = (const float*)d_in[3];
    const float* bn_b     = (const float*)d_in[4];
    const float* gcn_in_w = (const float*)d_in[5];
    const float* gcn_in_b = (const float*)d_in[6];
    const float* gcn_out_w= (const float*)d_in[7];
    const float* gcn_out_b= (const float*)d_in[8];
    const float* Wq       = (const float*)d_in[9];
    const float* Wk       = (const float*)d_in[10];
    const float* Wv       = (const float*)d_in[11];
    const float* Wo       = (const float*)d_in[12];
    const float* ln2_w    = (const float*)d_in[13];
    const float* ln2_b    = (const float*)d_in[14];
    const float* ln3_w    = (const float*)d_in[15];
    const float* ln3_b    = (const float*)d_in[16];
    const float* geglu_w  = (const float*)d_in[17];
    const float* geglu_b  = (const float*)d_in[18];
    const float* ffo_w    = (const float*)d_in[19];
    const float* ffo_b    = (const float*)d_in[20];
    float* out = (float*)d_out;

    float *h, *b1, *b2, *b3, *kb, *vb, *f;
    __nv_bfloat16 *bt0, *bt1, *cs;
    cudaGetSymbolAddress((void**)&h,  g_h);
    cudaGetSymbolAddress((void**)&b1, g_b1);
    cudaGetSymbolAddress((void**)&b2, g_b2);
    cudaGetSymbolAddress((void**)&b3, g_b3);
    cudaGetSymbolAddress((void**)&kb, g_kb);
    cudaGetSymbolAddress((void**)&vb, g_vb);
    cudaGetSymbolAddress((void**)&f,  g_f);
    cudaGetSymbolAddress((void**)&bt0, g_bt0);
    cudaGetSymbolAddress((void**)&bt1, g_bt1);
    cudaGetSymbolAddress((void**)&cs, g_cs);

    __nv_bfloat16* b1h = (__nv_bfloat16*)b1;
    __nv_bfloat16* b1l = b1h + (size_t)NN*DD;
    __nv_bfloat16* b3h = (__nv_bfloat16*)b3;
    __nv_bfloat16* b3l = b3h + (size_t)NN*DD;
    __nv_bfloat16* fh  = (__nv_bfloat16*)f;
    __nv_bfloat16* fl  = fh + (size_t)NN*2048;
    __nv_bfloat16* csh = cs;
    __nv_bfloat16* csl = cs + (size_t)BSZ*MM*DD;

    cudaFuncSetAttribute(attn_kernel,
                         cudaFuncAttributeMaxDynamicSharedMemorySize, ATT_SMEM);
    cudaFuncSetAttribute(mm_gemm,
                         cudaFuncAttributeMaxDynamicSharedMemorySize, MM_SMEM);

    const size_t OFF_GIN = 0, OFF_GOUT = 262144, OFF_L0 = 524288, PER_L = 4194304;
    auto G = [&](const __nv_bfloat16* Ah, const __nv_bfloat16* Al, size_t off,
                 float* C, int M, int N, int K, const float* bias, const float* add) {
        mm_gemm<<<dim3(N/128, M/128), 256, MM_SMEM>>>(
            Ah, Al, bt0 + off, bt1 + off, C, M, N, K, bias, add,
            nullptr, nullptr, 0);
    };

    // ---- prologue ----
    zero_stats<<<NN / 256, 256>>>();
    bn_partial<<<dim3(2, 16), 256>>>(x);
    bn_apply<<<(NN * DD / 4) / 256, 256>>>(x, bn_w, bn_b, b1h, b1l);
    wsplit<<<dim3(16, 16, 1), dim3(32, 8)>>>(gcn_in_w, bt0 + OFF_GIN,
                                             bt1 + OFF_GIN, 512, 512, 0, 0, 0);
    detect_kernel<<<1, 256>>>((const int*)edges);
    G(b1h, b1l, OFF_GIN, b2, NN, DD, DD, nullptr, nullptr);
    convert_kernel<<<(2*EE + 255) / 256, 256>>>(edges);
    deg_kernel<<<EE / 256, 256>>>();
    dinv_kernel<<<NN / 256, 256>>>();
    gcn_init<<<(NN * DD) / 256, 256>>>(b2, gcn_in_b, nullptr, h);
    gcn_scatter<<<EE / 8, 256>>>(b2, h);

    // remaining weight splits
    wsplit<<<dim3(16, 16, 1), dim3(32, 8)>>>(gcn_out_w, bt0 + OFF_GOUT, bt1 + OFF_GOUT, 512, 512, 0, 0, 0);
    wsplit<<<dim3(16, 16, 4), dim3(32, 8)>>>(Wq, bt0 + OFF_L0,          bt1 + OFF_L0,          512, 512, 262144, PER_L, 0);
    wsplit<<<dim3(16, 16, 4), dim3(32, 8)>>>(Wk, bt0 + OFF_L0 + 262144, bt1 + OFF_L0 + 262144, 512, 512, 262144, PER_L, 0);
    wsplit<<<dim3(16, 16, 4), dim3(32, 8)>>>(Wv, bt0 + OFF_L0 + 524288, bt1 + OFF_L0 + 524288, 512, 512, 262144, PER_L, 0);
    wsplit<<<dim3(16, 16, 4), dim3(32, 8)>>>(Wo, bt0 + OFF_L0 + 786432, bt1 + OFF_L0 + 786432, 512, 512, 262144, PER_L, 0);
    wsplit<<<dim3(128, 16, 4), dim3(32, 8)>>>(geglu_w, bt0 + OFF_L0 + 1048576, bt1 + OFF_L0 + 1048576, 512, 4096, 2097152, PER_L, 1);
    wsplit<<<dim3(16, 64, 4), dim3(32, 8)>>>(ffo_w, bt0 + OFF_L0 + 3145728, bt1 + OFF_L0 + 3145728, 2048, 512, 1048576, PER_L, 0);
    fsplit<<<(BSZ*MM*DD/4) / 256, 256>>>(cond, csh, csl);

    // ---- transformer layers ----
    for (int i = 0; i < LL; i++) {
        size_t base = OFF_L0 + (size_t)i * PER_L;
        ln_kernel<<<NN / 8, 256>>>(h, ln2_w + i*DD, ln2_b + i*DD, b1h, b1l);
        G(b1h, b1l, base,           b2, NN,     512, DD, nullptr, nullptr);
        G(csh, csl, base + 262144,  kb, BSZ*MM, 512, DD, nullptr, nullptr);
        G(csh, csl, base + 524288,  vb, BSZ*MM, 512, DD, nullptr, nullptr);
        attn_kernel<<<dim3(HH, BSZ, 4), 256, ATT_SMEM>>>(b2, kb, vb, b3h, b3l);
        G(b3h, b3l, base + 786432,  h,  NN,     DD,  512, nullptr, h);
        ln_kernel<<<NN / 8, 256>>>(h, ln3_w + i*DD, ln3_b + i*DD, b1h, b1l);
        // fused GEGLU GEMM: permuted weights, writes split-bf16 f planes
        mm_gemm<<<dim3(32, 128), 256, MM_SMEM>>>(
            b1h, b1l, bt0 + base + 1048576, bt1 + base + 1048576,
            nullptr, NN, 4096, DD, geglu_b + (size_t)i*4096, nullptr,
            fh, fl, 1);
        G(fh, fl,   base + 3145728, h,  NN,     DD, 2048, ffo_b + i*DD, h);
    }

    // ---- GCN out + residual ----
    fsplit<<<(NN*DD/4) / 256, 256>>>(h, b1h, b1l);
    G(b1h, b1l, OFF_GOUT, b2, NN, DD, DD, nullptr, nullptr);
    gcn_init<<<(NN * DD) / 256, 256>>>(b2, gcn_out_b, x, out);
    gcn_scatter<<<EE / 8, 256>>>(b2, out);
}

// round 14
// speedup vs baseline: 1.0370x; 1.0370x over previous
#include <cuda_runtime.h>
#include <cuda_bf16.h>
#include <math.h>
#include <stdint.h>

#define NN 16384
#define DD 512
#define BSZ 16
#define MM 256
#define HH 8
#define DHH 64
#define LL 4
#define EE 262144
#define EPSV 1e-5f

// ---------------- scratch (static device globals) ---------------------------
__device__ float g_h [(size_t)NN*DD];
__device__ float g_b1[(size_t)NN*DD];
__device__ float g_b2[(size_t)NN*DD];
__device__ float g_b3[(size_t)NN*DD];
__device__ float g_kb[(size_t)BSZ*MM*DD];
__device__ float g_vb[(size_t)BSZ*MM*DD];
__device__ float g_f [(size_t)NN*2048];
__device__ __nv_bfloat16 g_cs[(size_t)2*BSZ*MM*DD];
__device__ float g_deg [NN];
__device__ float g_dinv[NN];
__device__ int   g_edge[2*EE];
__device__ int   g_flag;
__device__ float g_sum  [DD];
__device__ float g_sumsq[DD];
#define WT_TOTAL 17301504ULL
__device__ __nv_bfloat16 g_bt0[WT_TOTAL];
__device__ __nv_bfloat16 g_bt1[WT_TOTAL];

// ======================= helpers =============================================
__device__ __forceinline__ uint32_t smem_u32(const void* p) {
    uint32_t a;
    asm("{ .reg .u64 t; cvta.to.shared.u64 t, %1; cvt.u32.u64 %0, t; }"
        : "=r"(a) : "l"(p));
    return a;
}
__device__ __forceinline__ uint32_t sw64(int row, int c) {
    return ((uint32_t)row << 6) + (((uint32_t)(c ^ ((row >> 1) & 3))) << 4);
}
__device__ __forceinline__ uint32_t asw(int row, int ch) {
    return ((uint32_t)row << 7) + (((uint32_t)(ch ^ (row & 7))) << 4);
}

#define LDSM_X4(r, addr) \
    asm volatile("ldmatrix.sync.aligned.m8n8.x4.shared.b16 {%0,%1,%2,%3}, [%4];" \
        : "=r"((r)[0]), "=r"((r)[1]), "=r"((r)[2]), "=r"((r)[3]) : "r"(addr))
#define LDSM_X4_T(r, addr) \
    asm volatile("ldmatrix.sync.aligned.m8n8.x4.trans.shared.b16 {%0,%1,%2,%3}, [%4];" \
        : "=r"((r)[0]), "=r"((r)[1]), "=r"((r)[2]), "=r"((r)[3]) : "r"(addr))

__device__ __forceinline__ void mma16816(float* c, const uint32_t* a, const uint32_t* b) {
    asm volatile("mma.sync.aligned.m16n8k16.row.col.f32.bf16.bf16.f32 "
        "{%0,%1,%2,%3}, {%4,%5,%6,%7}, {%8,%9}, {%0,%1,%2,%3};"
        : "+f"(c[0]), "+f"(c[1]), "+f"(c[2]), "+f"(c[3])
        : "r"(a[0]), "r"(a[1]), "r"(a[2]), "r"(a[3]), "r"(b[0]), "r"(b[1]));
}

#define CP_ASYNC16(dst, src) \
    asm volatile("cp.async.cg.shared.global [%0], [%1], 16;" :: "r"(dst), "l"(src))
#define CP_COMMIT()  asm volatile("cp.async.commit_group;" ::: "memory")
#define CP_WAIT1()   asm volatile("cp.async.wait_group 1;" ::: "memory")

__device__ __forceinline__ void split2(float a, float b, uint32_t& hi, uint32_t& lo) {
    __nv_bfloat16 ha = __float2bfloat16(a), hb = __float2bfloat16(b);
    __nv_bfloat162 H = __halves2bfloat162(ha, hb);
    __nv_bfloat162 L = __halves2bfloat162(
        __float2bfloat16(a - __bfloat162float(ha)),
        __float2bfloat16(b - __bfloat162float(hb)));
    hi = *(uint32_t*)&H; lo = *(uint32_t*)&L;
}

// ---------------- weight transpose + bf16 split (z-batched over layers) ------
// perm != 0: geglu column interleave — output row n' : orig col c<2048 -> 2c,
// c>=2048 -> 2(c-2048)+1, so (val,gate) pairs are adjacent columns.
__global__ void wsplit(const float* __restrict__ W, __nv_bfloat16* __restrict__ O0,
                       __nv_bfloat16* __restrict__ O1, int K, int N,
                       size_t wstride, size_t ostride, int perm) {
    __shared__ float t[32][33];
    W  += (size_t)blockIdx.z * wstride;
    O0 += (size_t)blockIdx.z * ostride;
    O1 += (size_t)blockIdx.z * ostride;
    int bn = blockIdx.x * 32, bk = blockIdx.y * 32;
    int tx = threadIdx.x, ty = threadIdx.y;
    for (int i = ty; i < 32; i += 8)
        t[i][tx] = W[(size_t)(bk + i) * N + bn + tx];
    __syncthreads();
    for (int i = ty; i < 32; i += 8) {
        float v = t[tx][i];
        __nv_bfloat16 h0 = __float2bfloat16(v);
        float r = v - __bfloat162float(h0);
        int n = bn + i;
        int dst = perm ? ((n < 2048) ? 2 * n : 2 * (n - 2048) + 1) : n;
        size_t o = (size_t)dst * K + bk + tx;
        O0[o] = h0;
        O1[o] = __float2bfloat16(r);
    }
}

// ---------------- fp32 -> split-bf16 planes ----------------------------------
__global__ void fsplit(const float* __restrict__ in, __nv_bfloat16* __restrict__ hi,
                       __nv_bfloat16* __restrict__ lo) {
    size_t i = (size_t)blockIdx.x * 256 + threadIdx.x;
    float4 v = ((const float4*)in)[i];
    uint32_t h0, h1, l0, l1;
    split2(v.x, v.y, h0, l0);
    split2(v.z, v.w, h1, l1);
    ((uint2*)hi)[i] = make_uint2(h0, h1);
    ((uint2*)lo)[i] = make_uint2(l0, l1);
}

// ---------------- HMMA split-bf16 GEMM, occupancy 2 --------------------------
// fuse=0: C = A*W (+bias)(+add) fp32.
// fuse=1: GEGLU epilogue — adjacent column pairs (val,gate); stages split-bf16
//         f tile in smem (pitch 72), then coalesced uint4 writes to f planes.
#define MM_SMEM 98304
#define STG 32768
#define FP 72              // staging pitch in bf16 elements (144B, 16B-aligned)
#define FPL 18432          // per-plane staging bytes: 128 * 144

__device__ __forceinline__ void mm_issue(
    const __nv_bfloat16* __restrict__ A0, const __nv_bfloat16* __restrict__ A1,
    const __nv_bfloat16* __restrict__ B0, const __nv_bfloat16* __restrict__ B1,
    uint32_t sb, int stage, int bm, int bn, int K, int kc, int tid)
{
    uint32_t a0b = sb + stage * STG, a1b = a0b + 8192;
    uint32_t b0b = a0b + 16384, b1b = a0b + 24576;
#pragma unroll
    for (int i = 0; i < 2; i++) {
        int idx = i * 256 + tid;
        int r = idx >> 2, c = idx & 3;
        uint32_t d = sw64(r, c);
        size_t sa = (size_t)(bm + r) * K + kc * 32 + c * 8;
        size_t sbx = (size_t)(bn + r) * K + kc * 32 + c * 8;
        CP_ASYNC16(a0b + d, A0 + sa);
        CP_ASYNC16(a1b + d, A1 + sa);
        CP_ASYNC16(b0b + d, B0 + sbx);
        CP_ASYNC16(b1b + d, B1 + sbx);
    }
}

__global__ __launch_bounds__(256, 2)
void mm_gemm(const __nv_bfloat16* __restrict__ A0, const __nv_bfloat16* __restrict__ A1,
             const __nv_bfloat16* __restrict__ B0, const __nv_bfloat16* __restrict__ B1,
             float* __restrict__ C, int M, int N, int K,
             const float* __restrict__ bias, const float* __restrict__ add,
             __nv_bfloat16* __restrict__ ohi, __nv_bfloat16* __restrict__ olo,
             int fuse)
{
    extern __shared__ char smem[];
    uint32_t sb = smem_u32(smem);
    const int tid = threadIdx.x, wid = tid >> 5, lane = tid & 31;
    const int bm = blockIdx.y * 128, bn = blockIdx.x * 128;
    const int wm = wid >> 2, wn = wid & 3;
    const int nch = K >> 5;

    float acc[4][4][4];
#pragma unroll
    for (int i = 0; i < 4; i++)
#pragma unroll
        for (int j = 0; j < 4; j++)
#pragma unroll
            for (int k = 0; k < 4; k++) acc[i][j][k] = 0.f;

    mm_issue(A0, A1, B0, B1, sb, 0, bm, bn, K, 0, tid); CP_COMMIT();
    mm_issue(A0, A1, B0, B1, sb, 1, bm, bn, K, 1, tid); CP_COMMIT();

    int pc = 0, pi = 2;
    for (int kc = 0; kc < nch; kc++) {
        CP_WAIT1();
        __syncthreads();
        if (kc + 2 < nch)
            mm_issue(A0, A1, B0, B1, sb, pi, bm, bn, K, kc + 2, tid);
        CP_COMMIT();

        const uint32_t stA0 = sb + pc * STG, stA1 = stA0 + 8192;
        const uint32_t stB0 = stA0 + 16384, stB1 = stA0 + 24576;
#pragma unroll
        for (int s = 0; s < 2; s++) {
            uint32_t rb0[2][4], rb1[2][4];
#pragma unroll
            for (int g = 0; g < 2; g++) {
                int row = wn * 32 + g * 16 + ((lane >> 4) << 3) + (lane & 7);
                int c = 2 * s + ((lane >> 3) & 1);
                uint32_t off = sw64(row, c);
                LDSM_X4(rb0[g], stB0 + off);
                LDSM_X4(rb1[g], stB1 + off);
            }
            uint32_t a[4][4];
            int arow = wm * 64 + (lane & 15);
            int ac = 2 * s + (lane >> 4);
#pragma unroll
            for (int mf = 0; mf < 4; mf++)
                LDSM_X4(a[mf], stA0 + sw64(arow + mf * 16, ac));
#pragma unroll
            for (int mf = 0; mf < 4; mf++)
#pragma unroll
                for (int g = 0; g < 2; g++) {
                    mma16816(acc[mf][2*g],   a[mf], rb0[g]);
                    mma16816(acc[mf][2*g+1], a[mf], rb0[g] + 2);
                    mma16816(acc[mf][2*g],   a[mf], rb1[g]);
                    mma16816(acc[mf][2*g+1], a[mf], rb1[g] + 2);
                }
#pragma unroll
            for (int mf = 0; mf < 4; mf++)
                LDSM_X4(a[mf], stA1 + sw64(arow + mf * 16, ac));
#pragma unroll
            for (int mf = 0; mf < 4; mf++)
#pragma unroll
                for (int g = 0; g < 2; g++) {
                    mma16816(acc[mf][2*g],   a[mf], rb0[g]);
                    mma16816(acc[mf][2*g+1], a[mf], rb0[g] + 2);
                }
        }
        pc = (pc == 2) ? 0 : pc + 1;
        pi = (pi == 2) ? 0 : pi + 1;
    }

    if (fuse) {
        // GEGLU epilogue: (c0,c0+1) = (val,gate); stage bf16 planes in smem,
        // then coalesced copy-out. Tile: 128 rows x 64 pcx per plane.
        __syncthreads();   // all warps done reading pipeline smem
        __nv_bfloat16* sh = (__nv_bfloat16*)smem;            // hi plane, pitch FP
        __nv_bfloat16* sl = (__nv_bfloat16*)(smem + FPL);    // lo plane
#pragma unroll
        for (int mf = 0; mf < 4; mf++) {
#pragma unroll
            for (int ng = 0; ng < 4; ng++) {
                int rl = wm * 64 + mf * 16 + (lane >> 2);
                int cl = wn * 16 + ng * 4 + (lane & 3);
                int pcx = (bn >> 1) + cl;
                float bv = bias[pcx], bg = bias[2048 + pcx];
                float val = acc[mf][ng][0] + bv, gate = acc[mf][ng][1] + bg;
                float f0 = val * 0.5f * gate * (1.f + erff(gate * 0.70710678f));
                val = acc[mf][ng][2] + bv; gate = acc[mf][ng][3] + bg;
                float f1 = val * 0.5f * gate * (1.f + erff(gate * 0.70710678f));
                __nv_bfloat16 h0 = __float2bfloat16(f0);
                sh[rl * FP + cl] = h0;
                sl[rl * FP + cl] = __float2bfloat16(f0 - __bfloat162float(h0));
                __nv_bfloat16 h1 = __float2bfloat16(f1);
                sh[(rl + 8) * FP + cl] = h1;
                sl[(rl + 8) * FP + cl] = __float2bfloat16(f1 - __bfloat162float(h1));
            }
        }
        __syncthreads();
        // copy-out: 2 threads per row, 4x uint4 (32 bf16) each, per plane
        int row = tid >> 1, halfp = tid & 1;
        size_t gb = (size_t)(bm + row) * 2048 + (bn >> 1) + halfp * 32;
        const uint4* srcH = (const uint4*)(smem + row * (FP * 2) + halfp * 64);
        const uint4* srcL = (const uint4*)(smem + FPL + row * (FP * 2) + halfp * 64);
        uint4* dstH = (uint4*)(ohi + gb);
        uint4* dstL = (uint4*)(olo + gb);
#pragma unroll
        for (int q = 0; q < 4; q++) dstH[q] = srcH[q];
#pragma unroll
        for (int q = 0; q < 4; q++) dstL[q] = srcL[q];
        return;
    }

#pragma unroll
    for (int mf = 0; mf < 4; mf++) {
#pragma unroll
        for (int ng = 0; ng < 4; ng++) {
            int r0 = bm + wm * 64 + mf * 16 + (lane >> 2);
            int c0 = bn + wn * 32 + ng * 8 + ((lane & 3) << 1);
            float2 v0 = make_float2(acc[mf][ng][0], acc[mf][ng][1]);
            float2 v1 = make_float2(acc[mf][ng][2], acc[mf][ng][3]);
            if (bias) {
                float2 bb = *(const float2*)(bias + c0);
                v0.x += bb.x; v0.y += bb.y; v1.x += bb.x; v1.y += bb.y;
            }
            if (add) {
                float2 a0v = *(const float2*)(add + (size_t)r0 * N + c0);
                float2 a1v = *(const float2*)(add + (size_t)(r0 + 8) * N + c0);
                v0.x += a0v.x; v0.y += a0v.y; v1.x += a1v.x; v1.y += a1v.y;
            }
            *(float2*)(C + (size_t)r0 * N + c0) = v0;
            *(float2*)(C + (size_t)(r0 + 8) * N + c0) = v1;
        }
    }
}

// ---------------- edge-index dtype detect + convert ------------------------
__global__ void detect_kernel(const int* __restrict__ e32) {
    __shared__ int any;
    if (threadIdx.x == 0) any = 0;
    __syncthreads();
    int bad = 0;
    for (int i = threadIdx.x; i < 4096; i += 256)
        if (e32[2*i + 1] != 0) bad = 1;
    if (bad) any = 1;
    __syncthreads();
    if (threadIdx.x == 0) g_flag = (any == 0) ? 1 : 0;
}

__global__ void convert_kernel(const void* __restrict__ e) {
    int i = blockIdx.x * 256 + threadIdx.x;
    if (i >= 2*EE) return;
    g_edge[i] = g_flag ? (int)((const long long*)e)[i] : ((const int*)e)[i];
}

__global__ void zero_stats() {
    int i = blockIdx.x * 256 + threadIdx.x;
    if (i < NN) g_deg[i] = 0.f;
    if (i < DD) { g_sum[i] = 0.f; g_sumsq[i] = 0.f; }
}

__global__ void deg_kernel() {
    int e = blockIdx.x * 256 + threadIdx.x;
    if (e < EE) atomicAdd(&g_deg[g_edge[EE + e]], 1.f);
}

__global__ void dinv_kernel() {
    int i = blockIdx.x * 256 + threadIdx.x;
    if (i < NN) g_dinv[i] = rsqrtf(g_deg[i] + 1.f);
}

// ---------------- BatchNorm --------------------------------------------------
__global__ void bn_partial(const float* __restrict__ x) {
    int col = blockIdx.x * 256 + threadIdx.x;
    int r0  = blockIdx.y * 1024;
    float s = 0.f, ss = 0.f;
    for (int r = r0; r < r0 + 1024; r++) {
        float v = x[(size_t)r * DD + col];
        s += v; ss += v * v;
    }
    atomicAdd(&g_sum[col], s);
    atomicAdd(&g_sumsq[col], ss);
}

__global__ void bn_apply(const float* __restrict__ x, const float* __restrict__ w,
                         const float* __restrict__ b, __nv_bfloat16* __restrict__ hi,
                         __nv_bfloat16* __restrict__ lo) {
    size_t i4 = (size_t)blockIdx.x * 256 + threadIdx.x;
    int c4 = (int)(i4 & 127) * 4;
    float4 xv = ((const float4*)x)[i4];
    float4 sm = *(const float4*)(g_sum + c4);
    float4 sq = *(const float4*)(g_sumsq + c4);
    float4 wv = *(const float4*)(w + c4);
    float4 bv = *(const float4*)(b + c4);
    float4 o;
    {
        float mu = sm.x / NN, var = sq.x / NN - mu*mu;
        o.x = (xv.x - mu) * rsqrtf(var + EPSV) * wv.x + bv.x;
        mu = sm.y / NN; var = sq.y / NN - mu*mu;
        o.y = (xv.y - mu) * rsqrtf(var + EPSV) * wv.y + bv.y;
        mu = sm.z / NN; var = sq.z / NN - mu*mu;
        o.z = (xv.z - mu) * rsqrtf(var + EPSV) * wv.z + bv.z;
        mu = sm.w / NN; var = sq.w / NN - mu*mu;
        o.w = (xv.w - mu) * rsqrtf(var + EPSV) * wv.w + bv.w;
    }
    uint32_t h0, h1, l0, l1;
    split2(o.x, o.y, h0, l0);
    split2(o.z, o.w, h1, l1);
    ((uint2*)hi)[i4] = make_uint2(h0, h1);
    ((uint2*)lo)[i4] = make_uint2(l0, l1);
}

// ---------------- LayerNorm -> split planes ----------------------------------
__global__ void ln_kernel(const float* __restrict__ x, const float* __restrict__ w,
                          const float* __restrict__ b, __nv_bfloat16* __restrict__ hi,
                          __nv_bfloat16* __restrict__ lo) {
    int warp = (blockIdx.x * blockDim.x + threadIdx.x) >> 5;
    int lane = threadIdx.x & 31;
    if (warp >= NN) return;
    const float4* xr = (const float4*)(x + (size_t)warp * DD);
    float4 v[4];
    float s = 0.f, ss = 0.f;
#pragma unroll
    for (int i = 0; i < 4; i++) {
        v[i] = xr[lane + 32*i];
        s  += v[i].x + v[i].y + v[i].z + v[i].w;
        ss += v[i].x*v[i].x + v[i].y*v[i].y + v[i].z*v[i].z + v[i].w*v[i].w;
    }
#pragma unroll
    for (int o = 16; o; o >>= 1) {
        s  += __shfl_xor_sync(0xffffffffu, s,  o);
        ss += __shfl_xor_sync(0xffffffffu, ss, o);
    }
    float mean = s * (1.f / DD);
    float var  = ss * (1.f / DD) - mean * mean;
    float rs   = rsqrtf(var + EPSV);
    uint2* hr = (uint2*)(hi + (size_t)warp * DD);
    uint2* lr = (uint2*)(lo + (size_t)warp * DD);
    const float4* wr = (const float4*)w;
    const float4* br = (const float4*)b;
#pragma unroll
    for (int i = 0; i < 4; i++) {
        float4 wv = wr[lane + 32*i], bv = br[lane + 32*i], o4;
        o4.x = (v[i].x - mean) * rs * wv.x + bv.x;
        o4.y = (v[i].y - mean) * rs * wv.y + bv.y;
        o4.z = (v[i].z - mean) * rs * wv.z + bv.z;
        o4.w = (v[i].w - mean) * rs * wv.w + bv.w;
        uint32_t h0, h1, l0, l1;
        split2(o4.x, o4.y, h0, l0);
        split2(o4.z, o4.w, h1, l1);
        hr[lane + 32*i] = make_uint2(h0, h1);
        lr[lane + 32*i] = make_uint2(l0, l1);
    }
}

// ---------------- GCN scatter ------------------------------------------------
__global__ void gcn_init(const float* __restrict__ hw, const float* __restrict__ bias,
                         const float* __restrict__ extra, float* __restrict__ out) {
    size_t i = (size_t)blockIdx.x * 256 + threadIdx.x;
    int r = (int)(i >> 9), c = (int)(i & 511);
    float dv = g_dinv[r];
    float v = hw[i] * dv * dv + bias[c];
    if (extra) v += extra[i];
    out[i] = v;
}

__global__ void gcn_scatter(const float* __restrict__ hw, float* __restrict__ out) {
    int wid  = (blockIdx.x * blockDim.x + threadIdx.x) >> 5;
    int lane = threadIdx.x & 31;
    if (wid >= EE) return;
    int s = g_edge[wid], d = g_edge[EE + wid];
    float w = g_dinv[s] * g_dinv[d];
    const float4* hp = (const float4*)(hw + (size_t)s * DD);
    float4* op = (float4*)(out + (size_t)d * DD);
#pragma unroll
    for (int i = 0; i < 4; i++) {
        int c = lane + 32 * i;
        float4 v = hp[c];
        v.x *= w; v.y *= w; v.z *= w; v.w *= w;
        atomicAdd(op + c, v);
    }
}

// ---------------- HMMA cross-attention (split-bf16, online softmax) ----------
#define ATT_SMEM 196608
#define OQH 0
#define OQL 32768
#define OKH 65536
#define OKL 98304
#define OVH 131072
#define OVL 163840

__global__ __launch_bounds__(256, 1) void attn_kernel(
    const float* __restrict__ Q, const float* __restrict__ Kc,
    const float* __restrict__ Vc, __nv_bfloat16* __restrict__ Ohi,
    __nv_bfloat16* __restrict__ Olo)
{
    extern __shared__ char smem[];
    uint32_t sb = smem_u32(smem);
    const int h = blockIdx.x, b = blockIdx.y, qc = blockIdx.z;
    const int tid = threadIdx.x, wid = tid >> 5, lane = tid & 31;
    const int qbase = b * 1024 + qc * 256;
    const int kbase = b * 256;

#pragma unroll 1
    for (int i = 0; i < 8; i++) {
        int idx = i * 256 + tid;
        int row = idx >> 3, ch = idx & 7;
        uint32_t d = asw(row, ch);
        uint32_t h0,h1,h2,h3,l0,l1,l2,l3;
        {
            const float* p = Q + (size_t)(qbase + row) * DD + h * DHH + ch * 8;
            float4 v0 = *(const float4*)p, v1 = *(const float4*)(p + 4);
            split2(v0.x, v0.y, h0, l0); split2(v0.z, v0.w, h1, l1);
            split2(v1.x, v1.y, h2, l2); split2(v1.z, v1.w, h3, l3);
            *(uint4*)(smem + OQH + d) = make_uint4(h0, h1, h2, h3);
            *(uint4*)(smem + OQL + d) = make_uint4(l0, l1, l2, l3);
        }
        {
            const float* p = Kc + (size_t)(kbase + row) * DD + h * DHH + ch * 8;
            float4 v0 = *(const float4*)p, v1 = *(const float4*)(p + 4);
            split2(v0.x, v0.y, h0, l0); split2(v0.z, v0.w, h1, l1);
            split2(v1.x, v1.y, h2, l2); split2(v1.z, v1.w, h3, l3);
            *(uint4*)(smem + OKH + d) = make_uint4(h0, h1, h2, h3);
            *(uint4*)(smem + OKL + d) = make_uint4(l0, l1, l2, l3);
        }
        {
            const float* p = Vc + (size_t)(kbase + row) * DD + h * DHH + ch * 8;
            float4 v0 = *(const float4*)p, v1 = *(const float4*)(p + 4);
            split2(v0.x, v0.y, h0, l0); split2(v0.z, v0.w, h1, l1);
            split2(v1.x, v1.y, h2, l2); split2(v1.z, v1.w, h3, l3);
            *(uint4*)(smem + OVH + d) = make_uint4(h0, h1, h2, h3);
            *(uint4*)(smem + OVL + d) = make_uint4(l0, l1, l2, l3);
        }
    }
    __syncthreads();

    const int wq = wid * 32;
    float oacc[2][8][4];
    float mrow[2][2], srow[2][2];
#pragma unroll
    for (int mf = 0; mf < 2; mf++) {
        mrow[mf][0] = -1e30f; mrow[mf][1] = -1e30f;
        srow[mf][0] = 0.f;    srow[mf][1] = 0.f;
#pragma unroll
        for (int nf = 0; nf < 8; nf++)
#pragma unroll
            for (int e = 0; e < 4; e++) oacc[mf][nf][e] = 0.f;
    }

#pragma unroll 1
    for (int kc4 = 0; kc4 < 4; kc4++) {
        float sacc[2][8][4];
#pragma unroll
        for (int mf = 0; mf < 2; mf++)
#pragma unroll
            for (int nf = 0; nf < 8; nf++)
#pragma unroll
                for (int e = 0; e < 4; e++) sacc[mf][nf][e] = 0.f;

#pragma unroll
        for (int ds = 0; ds < 4; ds++) {
            uint32_t qh[2][4], ql[2][4];
            int qrow = wq + (lane & 15);
            int qch = 2 * ds + (lane >> 4);
            LDSM_X4(qh[0], sb + OQH + asw(qrow, qch));
            LDSM_X4(qh[1], sb + OQH + asw(qrow + 16, qch));
            LDSM_X4(ql[0], sb + OQL + asw(qrow, qch));
            LDSM_X4(ql[1], sb + OQL + asw(qrow + 16, qch));
#pragma unroll
            for (int g = 0; g < 4; g++) {
                int krow = kc4 * 64 + g * 16 + ((lane >> 4) << 3) + (lane & 7);
                int kch = 2 * ds + ((lane >> 3) & 1);
                uint32_t kh[4], kl[4];
                LDSM_X4(kh, sb + OKH + asw(krow, kch));
                LDSM_X4(kl, sb + OKL + asw(krow, kch));
#pragma unroll
                for (int mf = 0; mf < 2; mf++) {
                    mma16816(sacc[mf][2*g],   qh[mf], kh);
                    mma16816(sacc[mf][2*g+1], qh[mf], kh + 2);
                    mma16816(sacc[mf][2*g],   qh[mf], kl);
                    mma16816(sacc[mf][2*g+1], qh[mf], kl + 2);
                    mma16816(sacc[mf][2*g],   ql[mf], kh);
                    mma16816(sacc[mf][2*g+1], ql[mf], kh + 2);
                }
            }
        }

#pragma unroll
        for (int mf = 0; mf < 2; mf++) {
            float mx0 = -1e30f, mx1 = -1e30f;
#pragma unroll
            for (int nf = 0; nf < 8; nf++) {
#pragma unroll
                for (int e = 0; e < 4; e++) sacc[mf][nf][e] *= 0.125f;
                mx0 = fmaxf(mx0, fmaxf(sacc[mf][nf][0], sacc[mf][nf][1]));
                mx1 = fmaxf(mx1, fmaxf(sacc[mf][nf][2], sacc[mf][nf][3]));
            }
            mx0 = fmaxf(mx0, __shfl_xor_sync(0xffffffffu, mx0, 1));
            mx0 = fmaxf(mx0, __shfl_xor_sync(0xffffffffu, mx0, 2));
            mx1 = fmaxf(mx1, __shfl_xor_sync(0xffffffffu, mx1, 1));
            mx1 = fmaxf(mx1, __shfl_xor_sync(0xffffffffu, mx1, 2));
            float nm0 = fmaxf(mrow[mf][0], mx0);
            float nm1 = fmaxf(mrow[mf][1], mx1);
            float c0 = __expf(mrow[mf][0] - nm0);
            float c1 = __expf(mrow[mf][1] - nm1);
            mrow[mf][0] = nm0; mrow[mf][1] = nm1;
            srow[mf][0] *= c0; srow[mf][1] *= c1;
#pragma unroll
            for (int nf = 0; nf < 8; nf++) {
                oacc[mf][nf][0] *= c0; oacc[mf][nf][1] *= c0;
                oacc[mf][nf][2] *= c1; oacc[mf][nf][3] *= c1;
                float p0 = __expf(sacc[mf][nf][0] - nm0);
                float p1 = __expf(sacc[mf][nf][1] - nm0);
                float p2 = __expf(sacc[mf][nf][2] - nm1);
                float p3 = __expf(sacc[mf][nf][3] - nm1);
                srow[mf][0] += p0 + p1;
                srow[mf][1] += p2 + p3;
                sacc[mf][nf][0] = p0; sacc[mf][nf][1] = p1;
                sacc[mf][nf][2] = p2; sacc[mf][nf][3] = p3;
            }
        }

#pragma unroll
        for (int kk = 0; kk < 4; kk++) {
            uint32_t p0f[2][4], p1f[2][4];
#pragma unroll
            for (int mf = 0; mf < 2; mf++) {
                const float* s0 = sacc[mf][2*kk];
                const float* s1 = sacc[mf][2*kk+1];
                split2(s0[0], s0[1], p0f[mf][0], p1f[mf][0]);
                split2(s0[2], s0[3], p0f[mf][1], p1f[mf][1]);
                split2(s1[0], s1[1], p0f[mf][2], p1f[mf][2]);
                split2(s1[2], s1[3], p0f[mf][3], p1f[mf][3]);
            }
            int vrow = kc4 * 64 + kk * 16 + (lane & 15);
#pragma unroll
            for (int g = 0; g < 4; g++) {
                int vch = 2 * g + (lane >> 4);
                uint32_t vh[4], vl[4];
                LDSM_X4_T(vh, sb + OVH + asw(vrow, vch));
                LDSM_X4_T(vl, sb + OVL + asw(vrow, vch));
#pragma unroll
                for (int mf = 0; mf < 2; mf++) {
                    mma16816(oacc[mf][2*g],   p0f[mf], vh);
                    mma16816(oacc[mf][2*g+1], p0f[mf], vh + 2);
                    mma16816(oacc[mf][2*g],   p0f[mf], vl);
                    mma16816(oacc[mf][2*g+1], p0f[mf], vl + 2);
                    mma16816(oacc[mf][2*g],   p1f[mf], vh);
                    mma16816(oacc[mf][2*g+1], p1f[mf], vh + 2);
                }
            }
        }
    }

#pragma unroll
    for (int mf = 0; mf < 2; mf++) {
        float s0 = srow[mf][0], s1 = srow[mf][1];
        s0 += __shfl_xor_sync(0xffffffffu, s0, 1);
        s0 += __shfl_xor_sync(0xffffffffu, s0, 2);
        s1 += __shfl_xor_sync(0xffffffffu, s1, 1);
        s1 += __shfl_xor_sync(0xffffffffu, s1, 2);
        float i0 = 1.f / s0, i1 = 1.f / s1;
        int r0 = qbase + wq + mf * 16 + (lane >> 2);
#pragma unroll
        for (int nf = 0; nf < 8; nf++) {
            int c = h * DHH + nf * 8 + ((lane & 3) << 1);
            uint32_t hh, lv;
            split2(oacc[mf][nf][0] * i0, oacc[mf][nf][1] * i0, hh, lv);
            *(uint32_t*)(Ohi + (size_t)r0 * DD + c) = hh;
            *(uint32_t*)(Olo + (size_t)r0 * DD + c) = lv;
            split2(oacc[mf][nf][2] * i1, oacc[mf][nf][3] * i1, hh, lv);
            *(uint32_t*)(Ohi + (size_t)(r0 + 8) * DD + c) = hh;
            *(uint32_t*)(Olo + (size_t)(r0 + 8) * DD + c) = lv;
        }
    }
}

// ---------------- host orchestration ----------------------------------------
extern "C" void kernel_launch(void* const* d_in, const int* in_sizes, int n_in,
                              void* d_out, int out_size)
{
    const float* x        = (const float*)d_in[0];
    const void*  edges    = d_in[1];
    const float* cond     = (const float*)d_in[2];
    const float* bn_w     = (const float*)d_in[3];
    const float* bn_b     = (const float*)d_in[4];
    const float* gcn_in_w = (const float*)d_in[5];
    const float* gcn_in_b = (const float*)d_in[6];
    const float* gcn_out_w= (const float*)d_in[7];
    const float* gcn_out_b= (const float*)d_in[8];
    const float* Wq       = (const float*)d_in[9];
    const float* Wk       = (const float*)d_in[10];
    const float* Wv       = (const float*)d_in[11];
    const float* Wo       = (const float*)d_in[12];
    const float* ln2_w    = (const float*)d_in[13];
    const float* ln2_b    = (const float*)d_in[14];
    const float* ln3_w    = (const float*)d_in[15];
    const float* ln3_b    = (const float*)d_in[16];
    const float* geglu_w  = (const float*)d_in[17];
    const float* geglu_b  = (const float*)d_in[18];
    const float* ffo_w    = (const float*)d_in[19];
    const float* ffo_b    = (const float*)d_in[20];
    float* out = (float*)d_out;

    float *h, *b1, *b2, *b3, *kb, *vb, *f;
    __nv_bfloat16 *bt0, *bt1, *cs;
    cudaGetSymbolAddress((void**)&h,  g_h);
    cudaGetSymbolAddress((void**)&b1, g_b1);
    cudaGetSymbolAddress((void**)&b2, g_b2);
    cudaGetSymbolAddress((void**)&b3, g_b3);
    cudaGetSymbolAddress((void**)&kb, g_kb);
    cudaGetSymbolAddress((void**)&vb, g_vb);
    cudaGetSymbolAddress((void**)&f,  g_f);
    cudaGetSymbolAddress((void**)&bt0, g_bt0);
    cudaGetSymbolAddress((void**)&bt1, g_bt1);
    cudaGetSymbolAddress((void**)&cs, g_cs);

    __nv_bfloat16* b1h = (__nv_bfloat16*)b1;
    __nv_bfloat16* b1l = b1h + (size_t)NN*DD;
    __nv_bfloat16* b3h = (__nv_bfloat16*)b3;
    __nv_bfloat16* b3l = b3h + (size_t)NN*DD;
    __nv_bfloat16* fh  = (__nv_bfloat16*)f;
    __nv_bfloat16* fl  = fh + (size_t)NN*2048;
    __nv_bfloat16* csh = cs;
    __nv_bfloat16* csl = cs + (size_t)BSZ*MM*DD;

    cudaFuncSetAttribute(attn_kernel,
                         cudaFuncAttributeMaxDynamicSharedMemorySize, ATT_SMEM);
    cudaFuncSetAttribute(mm_gemm,
                         cudaFuncAttributeMaxDynamicSharedMemorySize, MM_SMEM);

    const size_t OFF_GIN = 0, OFF_GOUT = 262144, OFF_L0 = 524288, PER_L = 4194304;
    auto G = [&](const __nv_bfloat16* Ah, const __nv_bfloat16* Al, size_t off,
                 float* C, int M, int N, int K, const float* bias, const float* add) {
        mm_gemm<<<dim3(N/128, M/128), 256, MM_SMEM>>>(
            Ah, Al, bt0 + off, bt1 + off, C, M, N, K, bias, add,
            nullptr, nullptr, 0);
    };

    // ---- prologue ----
    zero_stats<<<NN / 256, 256>>>();
    bn_partial<<<dim3(2, 16), 256>>>(x);
    bn_apply<<<(NN * DD / 4) / 256, 256>>>(x, bn_w, bn_b, b1h, b1l);
    wsplit<<<dim3(16, 16, 1), dim3(32, 8)>>>(gcn_in_w, bt0 + OFF_GIN,
                                             bt1 + OFF_GIN, 512, 512, 0, 0, 0);
    detect_kernel<<<1, 256>>>((const int*)edges);
    G(b1h, b1l, OFF_GIN, b2, NN, DD, DD, nullptr, nullptr);
    convert_kernel<<<(2*EE + 255) / 256, 256>>>(edges);
    deg_kernel<<<EE / 256, 256>>>();
    dinv_kernel<<<NN / 256, 256>>>();
    gcn_init<<<(NN * DD) / 256, 256>>>(b2, gcn_in_b, nullptr, h);
    gcn_scatter<<<EE / 8, 256>>>(b2, h);

    // remaining weight splits
    wsplit<<<dim3(16, 16, 1), dim3(32, 8)>>>(gcn_out_w, bt0 + OFF_GOUT, bt1 + OFF_GOUT, 512, 512, 0, 0, 0);
    wsplit<<<dim3(16, 16, 4), dim3(32, 8)>>>(Wq, bt0 + OFF_L0,          bt1 + OFF_L0,          512, 512, 262144, PER_L, 0);
    wsplit<<<dim3(16, 16, 4), dim3(32, 8)>>>(Wk, bt0 + OFF_L0 + 262144, bt1 + OFF_L0 + 262144, 512, 512, 262144, PER_L, 0);
    wsplit<<<dim3(16, 16, 4), dim3(32, 8)>>>(Wv, bt0 + OFF_L0 + 524288, bt1 + OFF_L0 + 524288, 512, 512, 262144, PER_L, 0);
    wsplit<<<dim3(16, 16, 4), dim3(32, 8)>>>(Wo, bt0 + OFF_L0 + 786432, bt1 + OFF_L0 + 786432, 512, 512, 262144, PER_L, 0);
    wsplit<<<dim3(128, 16, 4), dim3(32, 8)>>>(geglu_w, bt0 + OFF_L0 + 1048576, bt1 + OFF_L0 + 1048576, 512, 4096, 2097152, PER_L, 1);
    wsplit<<<dim3(16, 64, 4), dim3(32, 8)>>>(ffo_w, bt0 + OFF_L0 + 3145728, bt1 + OFF_L0 + 3145728, 2048, 512, 1048576, PER_L, 0);
    fsplit<<<(BSZ*MM*DD/4) / 256, 256>>>(cond, csh, csl);

    // ---- transformer layers ----
    for (int i = 0; i < LL; i++) {
        size_t base = OFF_L0 + (size_t)i * PER_L;
        ln_kernel<<<NN / 8, 256>>>(h, ln2_w + i*DD, ln2_b + i*DD, b1h, b1l);
        G(b1h, b1l, base,           b2, NN,     512, DD, nullptr, nullptr);
        G(csh, csl, base + 262144,  kb, BSZ*MM, 512, DD, nullptr, nullptr);
        G(csh, csl, base + 524288,  vb, BSZ*MM, 512, DD, nullptr, nullptr);
        attn_kernel<<<dim3(HH, BSZ, 4), 256, ATT_SMEM>>>(b2, kb, vb, b3h, b3l);
        G(b3h, b3l, base + 786432,  h,  NN,     DD,  512, nullptr, h);
        ln_kernel<<<NN / 8, 256>>>(h, ln3_w + i*DD, ln3_b + i*DD, b1h, b1l);
        // fused GEGLU GEMM: permuted weights, smem-staged coalesced f-plane writes
        mm_gemm<<<dim3(32, 128), 256, MM_SMEM>>>(
            b1h, b1l, bt0 + base + 1048576, bt1 + base + 1048576,
            nullptr, NN, 4096, DD, geglu_b + (size_t)i*4096, nullptr,
            fh, fl, 1);
        G(fh, fl,   base + 3145728, h,  NN,     DD, 2048, ffo_b + i*DD, h);
    }

    // ---- GCN out + residual ----
    fsplit<<<(NN*DD/4) / 256, 256>>>(h, b1h, b1l);
    G(b1h, b1l, OFF_GOUT, b2, NN, DD, DD, nullptr, nullptr);
    gcn_init<<<(NN * DD) / 256, 256>>>(b2, gcn_out_b, x, out);
    gcn_scatter<<<EE / 8, 256>>>(b2, out);
}

// round 17
// speedup vs baseline: 1.0669x; 1.0288x over previous
#include <cuda_runtime.h>
#include <cuda_bf16.h>
#include <math.h>
#include <stdint.h>

#define NN 16384
#define DD 512
#define BSZ 16
#define MM 256
#define HH 8
#define DHH 64
#define LL 4
#define EE 262144
#define EPSV 1e-5f

// ---------------- scratch (static device globals) ---------------------------
__device__ float g_h [(size_t)NN*DD];
__device__ float g_b1[(size_t)NN*DD];
__device__ float g_b2[(size_t)NN*DD];
__device__ float g_b3[(size_t)NN*DD];
__device__ float g_kvb[(size_t)BSZ*MM*1024];
__device__ float g_f [(size_t)NN*2048];
__device__ __nv_bfloat16 g_cs[(size_t)2*BSZ*MM*DD];
__device__ float g_dinv[NN];
__device__ int   g_edge[2*EE];
__device__ int   g_flag;
__device__ int   g_cnt [NN];
__device__ int   g_fill[NN];
__device__ int   g_off [NN + 1];
__device__ int   g_esrc[EE];
__device__ float g_ew  [EE];
__device__ float g_sum  [DD];
__device__ float g_sumsq[DD];
#define WT_TOTAL 17301504ULL
__device__ __nv_bfloat16 g_bt0[WT_TOTAL];
__device__ __nv_bfloat16 g_bt1[WT_TOTAL];

// ======================= helpers =============================================
__device__ __forceinline__ uint32_t smem_u32(const void* p) {
    uint32_t a;
    asm("{ .reg .u64 t; cvta.to.shared.u64 t, %1; cvt.u32.u64 %0, t; }"
        : "=r"(a) : "l"(p));
    return a;
}
__device__ __forceinline__ uint32_t sw64(int row, int c) {
    return ((uint32_t)row << 6) + (((uint32_t)(c ^ ((row >> 1) & 3))) << 4);
}
__device__ __forceinline__ uint32_t asw(int row, int ch) {
    return ((uint32_t)row << 7) + (((uint32_t)(ch ^ (row & 7))) << 4);
}

#define LDSM_X4(r, addr) \
    asm volatile("ldmatrix.sync.aligned.m8n8.x4.shared.b16 {%0,%1,%2,%3}, [%4];" \
        : "=r"((r)[0]), "=r"((r)[1]), "=r"((r)[2]), "=r"((r)[3]) : "r"(addr))
#define LDSM_X4_T(r, addr) \
    asm volatile("ldmatrix.sync.aligned.m8n8.x4.trans.shared.b16 {%0,%1,%2,%3}, [%4];" \
        : "=r"((r)[0]), "=r"((r)[1]), "=r"((r)[2]), "=r"((r)[3]) : "r"(addr))

__device__ __forceinline__ void mma16816(float* c, const uint32_t* a, const uint32_t* b) {
    asm volatile("mma.sync.aligned.m16n8k16.row.col.f32.bf16.bf16.f32 "
        "{%0,%1,%2,%3}, {%4,%5,%6,%7}, {%8,%9}, {%0,%1,%2,%3};"
        : "+f"(c[0]), "+f"(c[1]), "+f"(c[2]), "+f"(c[3])
        : "r"(a[0]), "r"(a[1]), "r"(a[2]), "r"(a[3]), "r"(b[0]), "r"(b[1]));
}

#define CP_ASYNC16(dst, src) \
    asm volatile("cp.async.cg.shared.global [%0], [%1], 16;" :: "r"(dst), "l"(src))
#define CP_COMMIT()  asm volatile("cp.async.commit_group;" ::: "memory")
#define CP_WAIT1()   asm volatile("cp.async.wait_group 1;" ::: "memory")

__device__ __forceinline__ void split2(float a, float b, uint32_t& hi, uint32_t& lo) {
    __nv_bfloat16 ha = __float2bfloat16(a), hb = __float2bfloat16(b);
    __nv_bfloat162 H = __halves2bfloat162(ha, hb);
    __nv_bfloat162 L = __halves2bfloat162(
        __float2bfloat16(a - __bfloat162float(ha)),
        __float2bfloat16(b - __bfloat162float(hb)));
    hi = *(uint32_t*)&H; lo = *(uint32_t*)&L;
}

// ---------------- weight transpose + bf16 split (z-batched over layers) ------
__global__ void wsplit(const float* __restrict__ W, __nv_bfloat16* __restrict__ O0,
                       __nv_bfloat16* __restrict__ O1, int K, int N,
                       size_t wstride, size_t ostride, int perm) {
    __shared__ float t[32][33];
    W  += (size_t)blockIdx.z * wstride;
    O0 += (size_t)blockIdx.z * ostride;
    O1 += (size_t)blockIdx.z * ostride;
    int bn = blockIdx.x * 32, bk = blockIdx.y * 32;
    int tx = threadIdx.x, ty = threadIdx.y;
    for (int i = ty; i < 32; i += 8)
        t[i][tx] = W[(size_t)(bk + i) * N + bn + tx];
    __syncthreads();
    for (int i = ty; i < 32; i += 8) {
        float v = t[tx][i];
        __nv_bfloat16 h0 = __float2bfloat16(v);
        float r = v - __bfloat162float(h0);
        int n = bn + i;
        int dst = perm ? ((n < 2048) ? 2 * n : 2 * (n - 2048) + 1) : n;
        size_t o = (size_t)dst * K + bk + tx;
        O0[o] = h0;
        O1[o] = __float2bfloat16(r);
    }
}

// ---------------- fp32 -> split-bf16 planes ----------------------------------
__global__ void fsplit(const float* __restrict__ in, __nv_bfloat16* __restrict__ hi,
                       __nv_bfloat16* __restrict__ lo) {
    size_t i = (size_t)blockIdx.x * 256 + threadIdx.x;
    float4 v = ((const float4*)in)[i];
    uint32_t h0, h1, l0, l1;
    split2(v.x, v.y, h0, l0);
    split2(v.z, v.w, h1, l1);
    ((uint2*)hi)[i] = make_uint2(h0, h1);
    ((uint2*)lo)[i] = make_uint2(l0, l1);
}

// ---------------- HMMA split-bf16 GEMM, occupancy 2 --------------------------
#define MM_SMEM 98304
#define STG 32768
#define FP 72
#define FPL 18432

__device__ __forceinline__ void mm_issue(
    const __nv_bfloat16* __restrict__ A0, const __nv_bfloat16* __restrict__ A1,
    const __nv_bfloat16* __restrict__ B0, const __nv_bfloat16* __restrict__ B1,
    uint32_t sb, int stage, int bm, int bn, int K, int kc, int tid)
{
    uint32_t a0b = sb + stage * STG, a1b = a0b + 8192;
    uint32_t b0b = a0b + 16384, b1b = a0b + 24576;
#pragma unroll
    for (int i = 0; i < 2; i++) {
        int idx = i * 256 + tid;
        int r = idx >> 2, c = idx & 3;
        uint32_t d = sw64(r, c);
        size_t sa = (size_t)(bm + r) * K + kc * 32 + c * 8;
        size_t sbx = (size_t)(bn + r) * K + kc * 32 + c * 8;
        CP_ASYNC16(a0b + d, A0 + sa);
        CP_ASYNC16(a1b + d, A1 + sa);
        CP_ASYNC16(b0b + d, B0 + sbx);
        CP_ASYNC16(b1b + d, B1 + sbx);
    }
}

__global__ __launch_bounds__(256, 2)
void mm_gemm(const __nv_bfloat16* __restrict__ A0, const __nv_bfloat16* __restrict__ A1,
             const __nv_bfloat16* __restrict__ B0, const __nv_bfloat16* __restrict__ B1,
             float* __restrict__ C, int M, int N, int K,
             const float* __restrict__ bias, const float* __restrict__ add,
             __nv_bfloat16* __restrict__ ohi, __nv_bfloat16* __restrict__ olo,
             int fuse)
{
    extern __shared__ char smem[];
    uint32_t sb = smem_u32(smem);
    const int tid = threadIdx.x, wid = tid >> 5, lane = tid & 31;
    const int bm = blockIdx.y * 128, bn = blockIdx.x * 128;
    const int wm = wid >> 2, wn = wid & 3;
    const int nch = K >> 5;

    float acc[4][4][4];
#pragma unroll
    for (int i = 0; i < 4; i++)
#pragma unroll
        for (int j = 0; j < 4; j++)
#pragma unroll
            for (int k = 0; k < 4; k++) acc[i][j][k] = 0.f;

    mm_issue(A0, A1, B0, B1, sb, 0, bm, bn, K, 0, tid); CP_COMMIT();
    mm_issue(A0, A1, B0, B1, sb, 1, bm, bn, K, 1, tid); CP_COMMIT();

    int pc = 0, pi = 2;
    for (int kc = 0; kc < nch; kc++) {
        CP_WAIT1();
        __syncthreads();
        if (kc + 2 < nch)
            mm_issue(A0, A1, B0, B1, sb, pi, bm, bn, K, kc + 2, tid);
        CP_COMMIT();

        const uint32_t stA0 = sb + pc * STG, stA1 = stA0 + 8192;
        const uint32_t stB0 = stA0 + 16384, stB1 = stA0 + 24576;
#pragma unroll
        for (int s = 0; s < 2; s++) {
            uint32_t rb0[2][4], rb1[2][4];
#pragma unroll
            for (int g = 0; g < 2; g++) {
                int row = wn * 32 + g * 16 + ((lane >> 4) << 3) + (lane & 7);
                int c = 2 * s + ((lane >> 3) & 1);
                uint32_t off = sw64(row, c);
                LDSM_X4(rb0[g], stB0 + off);
                LDSM_X4(rb1[g], stB1 + off);
            }
            uint32_t a[4][4];
            int arow = wm * 64 + (lane & 15);
            int ac = 2 * s + (lane >> 4);
#pragma unroll
            for (int mf = 0; mf < 4; mf++)
                LDSM_X4(a[mf], stA0 + sw64(arow + mf * 16, ac));
#pragma unroll
            for (int mf = 0; mf < 4; mf++)
#pragma unroll
                for (int g = 0; g < 2; g++) {
                    mma16816(acc[mf][2*g],   a[mf], rb0[g]);
                    mma16816(acc[mf][2*g+1], a[mf], rb0[g] + 2);
                    mma16816(acc[mf][2*g],   a[mf], rb1[g]);
                    mma16816(acc[mf][2*g+1], a[mf], rb1[g] + 2);
                }
#pragma unroll
            for (int mf = 0; mf < 4; mf++)
                LDSM_X4(a[mf], stA1 + sw64(arow + mf * 16, ac));
#pragma unroll
            for (int mf = 0; mf < 4; mf++)
#pragma unroll
                for (int g = 0; g < 2; g++) {
                    mma16816(acc[mf][2*g],   a[mf], rb0[g]);
                    mma16816(acc[mf][2*g+1], a[mf], rb0[g] + 2);
                }
        }
        pc = (pc == 2) ? 0 : pc + 1;
        pi = (pi == 2) ? 0 : pi + 1;
    }

    if (fuse) {
        __syncthreads();
        __nv_bfloat16* sh = (__nv_bfloat16*)smem;
        __nv_bfloat16* sl = (__nv_bfloat16*)(smem + FPL);
#pragma unroll
        for (int mf = 0; mf < 4; mf++) {
#pragma unroll
            for (int ng = 0; ng < 4; ng++) {
                int rl = wm * 64 + mf * 16 + (lane >> 2);
                int cl = wn * 16 + ng * 4 + (lane & 3);
                int pcx = (bn >> 1) + cl;
                float bv = bias[pcx], bg = bias[2048 + pcx];
                float val = acc[mf][ng][0] + bv, gate = acc[mf][ng][1] + bg;
                float f0 = val * 0.5f * gate * (1.f + erff(gate * 0.70710678f));
                val = acc[mf][ng][2] + bv; gate = acc[mf][ng][3] + bg;
                float f1 = val * 0.5f * gate * (1.f + erff(gate * 0.70710678f));
                __nv_bfloat16 h0 = __float2bfloat16(f0);
                sh[rl * FP + cl] = h0;
                sl[rl * FP + cl] = __float2bfloat16(f0 - __bfloat162float(h0));
                __nv_bfloat16 h1 = __float2bfloat16(f1);
                sh[(rl + 8) * FP + cl] = h1;
                sl[(rl + 8) * FP + cl] = __float2bfloat16(f1 - __bfloat162float(h1));
            }
        }
        __syncthreads();
        int row = tid >> 1, halfp = tid & 1;
        size_t gb = (size_t)(bm + row) * 2048 + (bn >> 1) + halfp * 32;
        const uint4* srcH = (const uint4*)(smem + row * (FP * 2) + halfp * 64);
        const uint4* srcL = (const uint4*)(smem + FPL + row * (FP * 2) + halfp * 64);
        uint4* dstH = (uint4*)(ohi + gb);
        uint4* dstL = (uint4*)(olo + gb);
#pragma unroll
        for (int q = 0; q < 4; q++) dstH[q] = srcH[q];
#pragma unroll
        for (int q = 0; q < 4; q++) dstL[q] = srcL[q];
        return;
    }

#pragma unroll
    for (int mf = 0; mf < 4; mf++) {
#pragma unroll
        for (int ng = 0; ng < 4; ng++) {
            int r0 = bm + wm * 64 + mf * 16 + (lane >> 2);
            int c0 = bn + wn * 32 + ng * 8 + ((lane & 3) << 1);
            float2 v0 = make_float2(acc[mf][ng][0], acc[mf][ng][1]);
            float2 v1 = make_float2(acc[mf][ng][2], acc[mf][ng][3]);
            if (bias) {
                float2 bb = *(const float2*)(bias + c0);
                v0.x += bb.x; v0.y += bb.y; v1.x += bb.x; v1.y += bb.y;
            }
            if (add) {
                float2 a0v = *(const float2*)(add + (size_t)r0 * N + c0);
                float2 a1v = *(const float2*)(add + (size_t)(r0 + 8) * N + c0);
                v0.x += a0v.x; v0.y += a0v.y; v1.x += a1v.x; v1.y += a1v.y;
            }
            *(float2*)(C + (size_t)r0 * N + c0) = v0;
            *(float2*)(C + (size_t)(r0 + 8) * N + c0) = v1;
        }
    }
}

// ---------------- edge-index dtype detect + convert ------------------------
__global__ void detect_kernel(const int* __restrict__ e32) {
    __shared__ int any;
    if (threadIdx.x == 0) any = 0;
    __syncthreads();
    int bad = 0;
    for (int i = threadIdx.x; i < 4096; i += 256)
        if (e32[2*i + 1] != 0) bad = 1;
    if (bad) any = 1;
    __syncthreads();
    if (threadIdx.x == 0) g_flag = (any == 0) ? 1 : 0;
}

__global__ void convert_kernel(const void* __restrict__ e) {
    int i = blockIdx.x * 256 + threadIdx.x;
    if (i >= 2*EE) return;
    g_edge[i] = g_flag ? (int)((const long long*)e)[i] : ((const int*)e)[i];
}

__global__ void zero_stats() {
    int i = blockIdx.x * 256 + threadIdx.x;
    if (i < NN) { g_cnt[i] = 0; g_fill[i] = 0; }
    if (i < DD) { g_sum[i] = 0.f; g_sumsq[i] = 0.f; }
}

__global__ void deg_kernel() {
    int e = blockIdx.x * 256 + threadIdx.x;
    if (e < EE) atomicAdd(&g_cnt[g_edge[EE + e]], 1);
}

__global__ void dinv_kernel() {
    int i = blockIdx.x * 256 + threadIdx.x;
    if (i < NN) g_dinv[i] = rsqrtf((float)g_cnt[i] + 1.f);
}

// exclusive prefix sum of g_cnt -> g_off (single block)
__global__ void scan_kernel() {
    __shared__ int part[256];
    int tid = threadIdx.x;
    int base = tid * 64;
    int s = 0;
    for (int i = 0; i < 64; i++) s += g_cnt[base + i];
    part[tid] = s;
    __syncthreads();
    if (tid == 0) {
        int acc = 0;
        for (int i = 0; i < 256; i++) { int t = part[i]; part[i] = acc; acc += t; }
        g_off[NN] = acc;
    }
    __syncthreads();
    int acc = part[tid];
    for (int i = 0; i < 64; i++) {
        g_off[base + i] = acc;
        acc += g_cnt[base + i];
    }
}

__global__ void bucket_kernel() {
    int e = blockIdx.x * 256 + threadIdx.x;
    if (e >= EE) return;
    int s = g_edge[e], d = g_edge[EE + e];
    int pos = g_off[d] + atomicAdd(&g_fill[d], 1);
    g_esrc[pos] = s;
    g_ew[pos] = g_dinv[s] * g_dinv[d];
}

// ---------------- BatchNorm --------------------------------------------------
__global__ void bn_partial(const float* __restrict__ x) {
    int col = blockIdx.x * 256 + threadIdx.x;
    int r0  = blockIdx.y * 1024;
    float s = 0.f, ss = 0.f;
    for (int r = r0; r < r0 + 1024; r++) {
        float v = x[(size_t)r * DD + col];
        s += v; ss += v * v;
    }
    atomicAdd(&g_sum[col], s);
    atomicAdd(&g_sumsq[col], ss);
}

__global__ void bn_apply(const float* __restrict__ x, const float* __restrict__ w,
                         const float* __restrict__ b, __nv_bfloat16* __restrict__ hi,
                         __nv_bfloat16* __restrict__ lo) {
    size_t i4 = (size_t)blockIdx.x * 256 + threadIdx.x;
    int c4 = (int)(i4 & 127) * 4;
    float4 xv = ((const float4*)x)[i4];
    float4 sm = *(const float4*)(g_sum + c4);
    float4 sq = *(const float4*)(g_sumsq + c4);
    float4 wv = *(const float4*)(w + c4);
    float4 bv = *(const float4*)(b + c4);
    float4 o;
    {
        float mu = sm.x / NN, var = sq.x / NN - mu*mu;
        o.x = (xv.x - mu) * rsqrtf(var + EPSV) * wv.x + bv.x;
        mu = sm.y / NN; var = sq.y / NN - mu*mu;
        o.y = (xv.y - mu) * rsqrtf(var + EPSV) * wv.y + bv.y;
        mu = sm.z / NN; var = sq.z / NN - mu*mu;
        o.z = (xv.z - mu) * rsqrtf(var + EPSV) * wv.z + bv.z;
        mu = sm.w / NN; var = sq.w / NN - mu*mu;
        o.w = (xv.w - mu) * rsqrtf(var + EPSV) * wv.w + bv.w;
    }
    uint32_t h0, h1, l0, l1;
    split2(o.x, o.y, h0, l0);
    split2(o.z, o.w, h1, l1);
    ((uint2*)hi)[i4] = make_uint2(h0, h1);
    ((uint2*)lo)[i4] = make_uint2(l0, l1);
}

// ---------------- LayerNorm -> split planes ----------------------------------
__global__ void ln_kernel(const float* __restrict__ x, const float* __restrict__ w,
                          const float* __restrict__ b, __nv_bfloat16* __restrict__ hi,
                          __nv_bfloat16* __restrict__ lo) {
    int warp = (blockIdx.x * blockDim.x + threadIdx.x) >> 5;
    int lane = threadIdx.x & 31;
    if (warp >= NN) return;
    const float4* xr = (const float4*)(x + (size_t)warp * DD);
    float4 v[4];
    float s = 0.f, ss = 0.f;
#pragma unroll
    for (int i = 0; i < 4; i++) {
        v[i] = xr[lane + 32*i];
        s  += v[i].x + v[i].y + v[i].z + v[i].w;
        ss += v[i].x*v[i].x + v[i].y*v[i].y + v[i].z*v[i].z + v[i].w*v[i].w;
    }
#pragma unroll
    for (int o = 16; o; o >>= 1) {
        s  += __shfl_xor_sync(0xffffffffu, s,  o);
        ss += __shfl_xor_sync(0xffffffffu, ss, o);
    }
    float mean = s * (1.f / DD);
    float var  = ss * (1.f / DD) - mean * mean;
    float rs   = rsqrtf(var + EPSV);
    uint2* hr = (uint2*)(hi + (size_t)warp * DD);
    uint2* lr = (uint2*)(lo + (size_t)warp * DD);
    const float4* wr = (const float4*)w;
    const float4* br = (const float4*)b;
#pragma unroll
    for (int i = 0; i < 4; i++) {
        float4 wv = wr[lane + 32*i], bv = br[lane + 32*i], o4;
        o4.x = (v[i].x - mean) * rs * wv.x + bv.x;
        o4.y = (v[i].y - mean) * rs * wv.y + bv.y;
        o4.z = (v[i].z - mean) * rs * wv.z + bv.z;
        o4.w = (v[i].w - mean) * rs * wv.w + bv.w;
        uint32_t h0, h1, l0, l1;
        split2(o4.x, o4.y, h0, l0);
        split2(o4.z, o4.w, h1, l1);
        hr[lane + 32*i] = make_uint2(h0, h1);
        lr[lane + 32*i] = make_uint2(l0, l1);
    }
}

// ---------------- GCN gather (atomic-free) -----------------------------------
// out[d,:] = sum_{e: dst=d} w_e * hw[src_e,:] + dinv[d]^2 * hw[d,:] + bias (+extra)
__global__ void gcn_gather(const float* __restrict__ hw, const float* __restrict__ bias,
                           const float* __restrict__ extra, float* __restrict__ out) {
    int node = (blockIdx.x * blockDim.x + threadIdx.x) >> 5;
    int lane = threadIdx.x & 31;
    if (node >= NN) return;
    float dv = g_dinv[node];
    float w0 = dv * dv;
    const float4* hp = (const float4*)(hw + (size_t)node * DD);
    float4 acc[4];
#pragma unroll
    for (int i = 0; i < 4; i++) {
        float4 v = hp[lane + 32*i];
        acc[i] = make_float4(v.x*w0, v.y*w0, v.z*w0, v.w*w0);
    }
    int e0 = g_off[node], e1 = g_off[node + 1];
    for (int e = e0; e < e1; e++) {
        int s = g_esrc[e];
        float w = g_ew[e];
        const float4* sp = (const float4*)(hw + (size_t)s * DD);
#pragma unroll
        for (int i = 0; i < 4; i++) {
            float4 v = sp[lane + 32*i];
            acc[i].x = fmaf(v.x, w, acc[i].x);
            acc[i].y = fmaf(v.y, w, acc[i].y);
            acc[i].z = fmaf(v.z, w, acc[i].z);
            acc[i].w = fmaf(v.w, w, acc[i].w);
        }
    }
    float4* op = (float4*)(out + (size_t)node * DD);
    const float4* bp = (const float4*)bias;
#pragma unroll
    for (int i = 0; i < 4; i++) {
        float4 b = bp[lane + 32*i];
        float4 r = acc[i];
        r.x += b.x; r.y += b.y; r.z += b.z; r.w += b.w;
        if (extra) {
            float4 xv = ((const float4*)(extra + (size_t)node * DD))[lane + 32*i];
            r.x += xv.x; r.y += xv.y; r.z += xv.z; r.w += xv.w;
        }
        op[lane + 32*i] = r;   // FIXED: was op[i]
    }
}

// ---------------- HMMA cross-attention (split-bf16, online softmax) ----------
// KV combined: row stride 1024, K at col 0, V at col 512.
#define ATT_SMEM 196608
#define OQH 0
#define OQL 32768
#define OKH 65536
#define OKL 98304
#define OVH 131072
#define OVL 163840

__global__ __launch_bounds__(256, 1) void attn_kernel(
    const float* __restrict__ Q, const float* __restrict__ KV,
    __nv_bfloat16* __restrict__ Ohi, __nv_bfloat16* __restrict__ Olo)
{
    extern __shared__ char smem[];
    uint32_t sb = smem_u32(smem);
    const int h = blockIdx.x, b = blockIdx.y, qc = blockIdx.z;
    const int tid = threadIdx.x, wid = tid >> 5, lane = tid & 31;
    const int qbase = b * 1024 + qc * 256;
    const int kbase = b * 256;

#pragma unroll 1
    for (int i = 0; i < 8; i++) {
        int idx = i * 256 + tid;
        int row = idx >> 3, ch = idx & 7;
        uint32_t d = asw(row, ch);
        uint32_t h0,h1,h2,h3,l0,l1,l2,l3;
        {
            const float* p = Q + (size_t)(qbase + row) * DD + h * DHH + ch * 8;
            float4 v0 = *(const float4*)p, v1 = *(const float4*)(p + 4);
            split2(v0.x, v0.y, h0, l0); split2(v0.z, v0.w, h1, l1);
            split2(v1.x, v1.y, h2, l2); split2(v1.z, v1.w, h3, l3);
            *(uint4*)(smem + OQH + d) = make_uint4(h0, h1, h2, h3);
            *(uint4*)(smem + OQL + d) = make_uint4(l0, l1, l2, l3);
        }
        {
            const float* p = KV + (size_t)(kbase + row) * 1024 + h * DHH + ch * 8;
            float4 v0 = *(const float4*)p, v1 = *(const float4*)(p + 4);
            split2(v0.x, v0.y, h0, l0); split2(v0.z, v0.w, h1, l1);
            split2(v1.x, v1.y, h2, l2); split2(v1.z, v1.w, h3, l3);
            *(uint4*)(smem + OKH + d) = make_uint4(h0, h1, h2, h3);
            *(uint4*)(smem + OKL + d) = make_uint4(l0, l1, l2, l3);
        }
        {
            const float* p = KV + (size_t)(kbase + row) * 1024 + 512 + h * DHH + ch * 8;
            float4 v0 = *(const float4*)p, v1 = *(const float4*)(p + 4);
            split2(v0.x, v0.y, h0, l0); split2(v0.z, v0.w, h1, l1);
            split2(v1.x, v1.y, h2, l2); split2(v1.z, v1.w, h3, l3);
            *(uint4*)(smem + OVH + d) = make_uint4(h0, h1, h2, h3);
            *(uint4*)(smem + OVL + d) = make_uint4(l0, l1, l2, l3);
        }
    }
    __syncthreads();

    const int wq = wid * 32;
    float oacc[2][8][4];
    float mrow[2][2], srow[2][2];
#pragma unroll
    for (int mf = 0; mf < 2; mf++) {
        mrow[mf][0] = -1e30f; mrow[mf][1] = -1e30f;
        srow[mf][0] = 0.f;    srow[mf][1] = 0.f;
#pragma unroll
        for (int nf = 0; nf < 8; nf++)
#pragma unroll
            for (int e = 0; e < 4; e++) oacc[mf][nf][e] = 0.f;
    }

#pragma unroll 1
    for (int kc4 = 0; kc4 < 4; kc4++) {
        float sacc[2][8][4];
#pragma unroll
        for (int mf = 0; mf < 2; mf++)
#pragma unroll
            for (int nf = 0; nf < 8; nf++)
#pragma unroll
                for (int e = 0; e < 4; e++) sacc[mf][nf][e] = 0.f;

#pragma unroll
        for (int ds = 0; ds < 4; ds++) {
            uint32_t qh[2][4], ql[2][4];
            int qrow = wq + (lane & 15);
            int qch = 2 * ds + (lane >> 4);
            LDSM_X4(qh[0], sb + OQH + asw(qrow, qch));
            LDSM_X4(qh[1], sb + OQH + asw(qrow + 16, qch));
            LDSM_X4(ql[0], sb + OQL + asw(qrow, qch));
            LDSM_X4(ql[1], sb + OQL + asw(qrow + 16, qch));
#pragma unroll
            for (int g = 0; g < 4; g++) {
                int krow = kc4 * 64 + g * 16 + ((lane >> 4) << 3) + (lane & 7);
                int kch = 2 * ds + ((lane >> 3) & 1);
                uint32_t kh[4], kl[4];
                LDSM_X4(kh, sb + OKH + asw(krow, kch));
                LDSM_X4(kl, sb + OKL + asw(krow, kch));
#pragma unroll
                for (int mf = 0; mf < 2; mf++) {
                    mma16816(sacc[mf][2*g],   qh[mf], kh);
                    mma16816(sacc[mf][2*g+1], qh[mf], kh + 2);
                    mma16816(sacc[mf][2*g],   qh[mf], kl);
                    mma16816(sacc[mf][2*g+1], qh[mf], kl + 2);
                    mma16816(sacc[mf][2*g],   ql[mf], kh);
                    mma16816(sacc[mf][2*g+1], ql[mf], kh + 2);
                }
            }
        }

#pragma unroll
        for (int mf = 0; mf < 2; mf++) {
            float mx0 = -1e30f, mx1 = -1e30f;
#pragma unroll
            for (int nf = 0; nf < 8; nf++) {
#pragma unroll
                for (int e = 0; e < 4; e++) sacc[mf][nf][e] *= 0.125f;
                mx0 = fmaxf(mx0, fmaxf(sacc[mf][nf][0], sacc[mf][nf][1]));
                mx1 = fmaxf(mx1, fmaxf(sacc[mf][nf][2], sacc[mf][nf][3]));
            }
            mx0 = fmaxf(mx0, __shfl_xor_sync(0xffffffffu, mx0, 1));
            mx0 = fmaxf(mx0, __shfl_xor_sync(0xffffffffu, mx0, 2));
            mx1 = fmaxf(mx1, __shfl_xor_sync(0xffffffffu, mx1, 1));
            mx1 = fmaxf(mx1, __shfl_xor_sync(0xffffffffu, mx1, 2));
            float nm0 = fmaxf(mrow[mf][0], mx0);
            float nm1 = fmaxf(mrow[mf][1], mx1);
            float c0 = __expf(mrow[mf][0] - nm0);
            float c1 = __expf(mrow[mf][1] - nm1);
            mrow[mf][0] = nm0; mrow[mf][1] = nm1;
            srow[mf][0] *= c0; srow[mf][1] *= c1;
#pragma unroll
            for (int nf = 0; nf < 8; nf++) {
                oacc[mf][nf][0] *= c0; oacc[mf][nf][1] *= c0;
                oacc[mf][nf][2] *= c1; oacc[mf][nf][3] *= c1;
                float p0 = __expf(sacc[mf][nf][0] - nm0);
                float p1 = __expf(sacc[mf][nf][1] - nm0);
                float p2 = __expf(sacc[mf][nf][2] - nm1);
                float p3 = __expf(sacc[mf][nf][3] - nm1);
                srow[mf][0] += p0 + p1;
                srow[mf][1] += p2 + p3;
                sacc[mf][nf][0] = p0; sacc[mf][nf][1] = p1;
                sacc[mf][nf][2] = p2; sacc[mf][nf][3] = p3;
            }
        }

#pragma unroll
        for (int kk = 0; kk < 4; kk++) {
            uint32_t p0f[2][4], p1f[2][4];
#pragma unroll
            for (int mf = 0; mf < 2; mf++) {
                const float* s0 = sacc[mf][2*kk];
                const float* s1 = sacc[mf][2*kk+1];
                split2(s0[0], s0[1], p0f[mf][0], p1f[mf][0]);
                split2(s0[2], s0[3], p0f[mf][1], p1f[mf][1]);
                split2(s1[0], s1[1], p0f[mf][2], p1f[mf][2]);
                split2(s1[2], s1[3], p0f[mf][3], p1f[mf][3]);
            }
            int vrow = kc4 * 64 + kk * 16 + (lane & 15);
#pragma unroll
            for (int g = 0; g < 4; g++) {
                int vch = 2 * g + (lane >> 4);
                uint32_t vh[4], vl[4];
                LDSM_X4_T(vh, sb + OVH + asw(vrow, vch));
                LDSM_X4_T(vl, sb + OVL + asw(vrow, vch));
#pragma unroll
                for (int mf = 0; mf < 2; mf++) {
                    mma16816(oacc[mf][2*g],   p0f[mf], vh);
                    mma16816(oacc[mf][2*g+1], p0f[mf], vh + 2);
                    mma16816(oacc[mf][2*g],   p0f[mf], vl);
                    mma16816(oacc[mf][2*g+1], p0f[mf], vl + 2);
                    mma16816(oacc[mf][2*g],   p1f[mf], vh);
                    mma16816(oacc[mf][2*g+1], p1f[mf], vh + 2);
                }
            }
        }
    }

#pragma unroll
    for (int mf = 0; mf < 2; mf++) {
        float s0 = srow[mf][0], s1 = srow[mf][1];
        s0 += __shfl_xor_sync(0xffffffffu, s0, 1);
        s0 += __shfl_xor_sync(0xffffffffu, s0, 2);
        s1 += __shfl_xor_sync(0xffffffffu, s1, 1);
        s1 += __shfl_xor_sync(0xffffffffu, s1, 2);
        float i0 = 1.f / s0, i1 = 1.f / s1;
        int r0 = qbase + wq + mf * 16 + (lane >> 2);
#pragma unroll
        for (int nf = 0; nf < 8; nf++) {
            int c = h * DHH + nf * 8 + ((lane & 3) << 1);
            uint32_t hh, lv;
            split2(oacc[mf][nf][0] * i0, oacc[mf][nf][1] * i0, hh, lv);
            *(uint32_t*)(Ohi + (size_t)r0 * DD + c) = hh;
            *(uint32_t*)(Olo + (size_t)r0 * DD + c) = lv;
            split2(oacc[mf][nf][2] * i1, oacc[mf][nf][3] * i1, hh, lv);
            *(uint32_t*)(Ohi + (size_t)(r0 + 8) * DD + c) = hh;
            *(uint32_t*)(Olo + (size_t)(r0 + 8) * DD + c) = lv;
        }
    }
}

// ---------------- host orchestration ----------------------------------------
extern "C" void kernel_launch(void* const* d_in, const int* in_sizes, int n_in,
                              void* d_out, int out_size)
{
    const float* x        = (const float*)d_in[0];
    const void*  edges    = d_in[1];
    const float* cond     = (const float*)d_in[2];
    const float* bn_w     = (const float*)d_in[3];
    const float* bn_b     = (const float*)d_in[4];
    const float* gcn_in_w = (const float*)d_in[5];
    const float* gcn_in_b = (const float*)d_in[6];
    const float* gcn_out_w= (const float*)d_in[7];
    const float* gcn_out_b= (const float*)d_in[8];
    const float* Wq       = (const float*)d_in[9];
    const float* Wk       = (const float*)d_in[10];
    const float* Wv       = (const float*)d_in[11];
    const float* Wo       = (const float*)d_in[12];
    const float* ln2_w    = (const float*)d_in[13];
    const float* ln2_b    = (const float*)d_in[14];
    const float* ln3_w    = (const float*)d_in[15];
    const float* ln3_b    = (const float*)d_in[16];
    const float* geglu_w  = (const float*)d_in[17];
    const float* geglu_b  = (const float*)d_in[18];
    const float* ffo_w    = (const float*)d_in[19];
    const float* ffo_b    = (const float*)d_in[20];
    float* out = (float*)d_out;

    float *h, *b1, *b2, *b3, *kvb, *f;
    __nv_bfloat16 *bt0, *bt1, *cs;
    cudaGetSymbolAddress((void**)&h,  g_h);
    cudaGetSymbolAddress((void**)&b1, g_b1);
    cudaGetSymbolAddress((void**)&b2, g_b2);
    cudaGetSymbolAddress((void**)&b3, g_b3);
    cudaGetSymbolAddress((void**)&kvb, g_kvb);
    cudaGetSymbolAddress((void**)&f,  g_f);
    cudaGetSymbolAddress((void**)&bt0, g_bt0);
    cudaGetSymbolAddress((void**)&bt1, g_bt1);
    cudaGetSymbolAddress((void**)&cs, g_cs);

    __nv_bfloat16* b1h = (__nv_bfloat16*)b1;
    __nv_bfloat16* b1l = b1h + (size_t)NN*DD;
    __nv_bfloat16* b3h = (__nv_bfloat16*)b3;
    __nv_bfloat16* b3l = b3h + (size_t)NN*DD;
    __nv_bfloat16* fh  = (__nv_bfloat16*)f;
    __nv_bfloat16* fl  = fh + (size_t)NN*2048;
    __nv_bfloat16* csh = cs;
    __nv_bfloat16* csl = cs + (size_t)BSZ*MM*DD;

    cudaFuncSetAttribute(attn_kernel,
                         cudaFuncAttributeMaxDynamicSharedMemorySize, ATT_SMEM);
    cudaFuncSetAttribute(mm_gemm,
                         cudaFuncAttributeMaxDynamicSharedMemorySize, MM_SMEM);

    const size_t OFF_GIN = 0, OFF_GOUT = 262144, OFF_L0 = 524288, PER_L = 4194304;
    auto G = [&](const __nv_bfloat16* Ah, const __nv_bfloat16* Al, size_t off,
                 float* C, int M, int N, int K, const float* bias, const float* add) {
        mm_gemm<<<dim3(N/128, M/128), 256, MM_SMEM>>>(
            Ah, Al, bt0 + off, bt1 + off, C, M, N, K, bias, add,
            nullptr, nullptr, 0);
    };

    // ---- prologue ----
    zero_stats<<<NN / 256, 256>>>();
    bn_partial<<<dim3(2, 16), 256>>>(x);
    bn_apply<<<(NN * DD / 4) / 256, 256>>>(x, bn_w, bn_b, b1h, b1l);
    wsplit<<<dim3(16, 16, 1), dim3(32, 8)>>>(gcn_in_w, bt0 + OFF_GIN,
                                             bt1 + OFF_GIN, 512, 512, 0, 0, 0);
    detect_kernel<<<1, 256>>>((const int*)edges);
    G(b1h, b1l, OFF_GIN, b2, NN, DD, DD, nullptr, nullptr);
    convert_kernel<<<(2*EE + 255) / 256, 256>>>(edges);
    deg_kernel<<<EE / 256, 256>>>();
    dinv_kernel<<<NN / 256, 256>>>();
    scan_kernel<<<1, 256>>>();
    bucket_kernel<<<EE / 256, 256>>>();
    gcn_gather<<<NN / 8, 256>>>(b2, gcn_in_b, nullptr, h);

    // remaining weight splits (Wk/Wv contiguous -> combined KV GEMM later)
    wsplit<<<dim3(16, 16, 1), dim3(32, 8)>>>(gcn_out_w, bt0 + OFF_GOUT, bt1 + OFF_GOUT, 512, 512, 0, 0, 0);
    wsplit<<<dim3(16, 16, 4), dim3(32, 8)>>>(Wq, bt0 + OFF_L0,          bt1 + OFF_L0,          512, 512, 262144, PER_L, 0);
    wsplit<<<dim3(16, 16, 4), dim3(32, 8)>>>(Wk, bt0 + OFF_L0 + 262144, bt1 + OFF_L0 + 262144, 512, 512, 262144, PER_L, 0);
    wsplit<<<dim3(16, 16, 4), dim3(32, 8)>>>(Wv, bt0 + OFF_L0 + 524288, bt1 + OFF_L0 + 524288, 512, 512, 262144, PER_L, 0);
    wsplit<<<dim3(16, 16, 4), dim3(32, 8)>>>(Wo, bt0 + OFF_L0 + 786432, bt1 + OFF_L0 + 786432, 512, 512, 262144, PER_L, 0);
    wsplit<<<dim3(128, 16, 4), dim3(32, 8)>>>(geglu_w, bt0 + OFF_L0 + 1048576, bt1 + OFF_L0 + 1048576, 512, 4096, 2097152, PER_L, 1);
    wsplit<<<dim3(16, 64, 4), dim3(32, 8)>>>(ffo_w, bt0 + OFF_L0 + 3145728, bt1 + OFF_L0 + 3145728, 2048, 512, 1048576, PER_L, 0);
    fsplit<<<(BSZ*MM*DD/4) / 256, 256>>>(cond, csh, csl);

    // ---- transformer layers ----
    for (int i = 0; i < LL; i++) {
        size_t base = OFF_L0 + (size_t)i * PER_L;
        ln_kernel<<<NN / 8, 256>>>(h, ln2_w + i*DD, ln2_b + i*DD, b1h, b1l);
        G(b1h, b1l, base,           b2,  NN,     512,  DD, nullptr, nullptr);
        // combined K+V projection: Wk rows 0-511, Wv rows 512-1023 (contiguous)
        G(csh, csl, base + 262144,  kvb, BSZ*MM, 1024, DD, nullptr, nullptr);
        attn_kernel<<<dim3(HH, BSZ, 4), 256, ATT_SMEM>>>(b2, kvb, b3h, b3l);
        G(b3h, b3l, base + 786432,  h,   NN,     DD,   512, nullptr, h);
        ln_kernel<<<NN / 8, 256>>>(h, ln3_w + i*DD, ln3_b + i*DD, b1h, b1l);
        mm_gemm<<<dim3(32, 128), 256, MM_SMEM>>>(
            b1h, b1l, bt0 + base + 1048576, bt1 + base + 1048576,
            nullptr, NN, 4096, DD, geglu_b + (size_t)i*4096, nullptr,
            fh, fl, 1);
        G(fh, fl,   base + 3145728, h,   NN,     DD,  2048, ffo_b + i*DD, h);
    }

    // ---- GCN out + residual ----
    fsplit<<<(NN*DD/4) / 256, 256>>>(h, b1h, b1l);
    G(b1h, b1l, OFF_GOUT, b2, NN, DD, DD, nullptr, nullptr);
    gcn_gather<<<NN / 8, 256>>>(b2, gcn_out_b, x, out);
}